// round 2
// baseline (speedup 1.0000x reference)
#include <cuda_runtime.h>
#include <math.h>

#define KK 256
#define CC 256
#define PP 196
#define OSZ 14
#define HH 112
#define WW 112
#define BB 4
#define HWSZ 12544
#define NODES 196

// ---------------- scratch (static device allocations) ----------------
__device__ float g_semT[BB * HWSZ * CC];      // semantic NHWC
__device__ float g_roisem[KK * PP * CC];      // roi_sem NHWC [k][p][c]
__device__ float g_bnsem[KK * CC * PP];       // bn_relu(roi_sem) NCHW
__device__ float g_bnfpn[KK * CC * PP];       // bn_relu(roi_feature) NCHW
__device__ float g_abuf[KK * 64 * PP];        // conv sum 'a' NCHW
__device__ float g_Abuf[KK * PP * PP];        // sigmoid affinity A[k][i][j]
__device__ float g_dis[KK * PP];              // rsqrt(deg)
__device__ float g_xw1[KK * PP * 16];         // dis_i * (X @ w1)
__device__ float g_xw2[KK * PP * CC];         // dis_i * (x1 @ w2)
__device__ float g_wsemT[CC * 9 * 64];        // w [ic][tap][oc]
__device__ float g_wfpnT[CC * 9 * 64];
__device__ float g_waffT[64 * PP];            // w_aff [c][n]
__device__ float g_sc_sem[CC], g_sh_sem[CC];
__device__ float g_sc_fpn[CC], g_sh_fpn[CC];
__device__ float g_sc_aff[64], g_sh_aff[64];

// ---------------- prep: bn scale/shift ----------------
__global__ void k_prep_scale(const float* gs, const float* bs, const float* ms, const float* vs,
                             const float* gf, const float* bf, const float* mf, const float* vf,
                             const float* ga, const float* ba, const float* ma, const float* va) {
    int t = threadIdx.x;
    if (t < CC) {
        float s = gs[t] * rsqrtf(vs[t] + 1e-5f);
        g_sc_sem[t] = s;
        g_sh_sem[t] = bs[t] - ms[t] * s;
        float f = gf[t] * rsqrtf(vf[t] + 1e-5f);
        g_sc_fpn[t] = f;
        g_sh_fpn[t] = bf[t] - mf[t] * f;
    }
    if (t < 64) {
        float a = ga[t] * rsqrtf(va[t] + 1e-5f);
        g_sc_aff[t] = a;
        g_sh_aff[t] = ba[t] - ma[t] * a;
    }
}

// ---------------- prep: weight transposes ----------------
__global__ void k_prep_wt(const float* wsem, const float* wfpn, const float* waff) {
    const int N1 = CC * 9 * 64;       // 147456
    const int NA = 64 * PP;           // 12544
    int total = 2 * N1 + NA;
    for (int d = blockIdx.x * blockDim.x + threadIdx.x; d < total; d += gridDim.x * blockDim.x) {
        if (d < N1) {
            int ic = d / 576, r = d % 576, tap = r / 64, oc = r % 64;
            g_wsemT[d] = wsem[oc * (CC * 9) + ic * 9 + tap];
        } else if (d < 2 * N1) {
            int e = d - N1;
            int ic = e / 576, r = e % 576, tap = r / 64, oc = r % 64;
            g_wfpnT[e] = wfpn[oc * (CC * 9) + ic * 9 + tap];
        } else {
            int e = d - 2 * N1;
            int c = e / PP, n = e % PP;
            g_waffT[e] = waff[n * 64 + c];
        }
    }
}

// ---------------- transpose semantic NCHW -> NHWC ----------------
__global__ void k_trans_sem(const float* __restrict__ sem) {
    __shared__ float tile[32][33];
    int b = blockIdx.z;
    int hw0 = blockIdx.x * 32;
    int c0 = blockIdx.y * 32;
    int tx = threadIdx.x, ty = threadIdx.y;
    const float* src = sem + (size_t)b * CC * HWSZ;
    float* dst = g_semT + (size_t)b * HWSZ * CC;
#pragma unroll
    for (int yy = 0; yy < 32; yy += 8)
        tile[ty + yy][tx] = src[(size_t)(c0 + ty + yy) * HWSZ + hw0 + tx];
    __syncthreads();
#pragma unroll
    for (int yy = 0; yy < 32; yy += 8)
        dst[(size_t)(hw0 + ty + yy) * CC + c0 + tx] = tile[tx][ty + yy];
}

// ---------------- bn_relu(roi_feature) ----------------
__global__ void k_bnfpn(const float* __restrict__ rf) {
    int idx = blockIdx.x * 256 + threadIdx.x;
    if (idx >= KK * CC * PP) return;
    int c = (idx / PP) % CC;
    float v = rf[idx] * g_sc_fpn[c] + g_sh_fpn[c];
    g_bnfpn[idx] = fmaxf(v, 0.f);
}

// ---------------- ROI align ----------------
__global__ void k_roialign(const float* __restrict__ boxes) {
    int p = blockIdx.x;           // 0..195
    int k = blockIdx.y;           // 0..255
    int c = threadIdx.x;          // 0..255
    int bidx = (int)boxes[k * 5 + 0];
    float x1 = boxes[k * 5 + 1], y1 = boxes[k * 5 + 2];
    float x2 = boxes[k * 5 + 3], y2 = boxes[k * 5 + 4];
    float bw = fmaxf(x2 - x1, 1.f) * (1.f / OSZ);
    float bh = fmaxf(y2 - y1, 1.f) * (1.f / OSZ);
    int oy = p / OSZ, ox = p % OSZ;
    const float* base = g_semT + (size_t)bidx * HWSZ * CC;
    float acc = 0.f;
#pragma unroll
    for (int s = 0; s < 4; s++) {
        int sy = oy * 2 + (s >> 1);
        int sx = ox * 2 + (s & 1);
        float yv = y1 + bh * ((sy + 0.5f) * 0.5f);
        float xv = x1 + bw * ((sx + 0.5f) * 0.5f);
        bool m = (yv >= -1.f) && (yv <= (float)HH) && (xv >= -1.f) && (xv <= (float)WW);
        float yc = fminf(fmaxf(yv, 0.f), (float)(HH - 1));
        float xc = fminf(fmaxf(xv, 0.f), (float)(WW - 1));
        int yl = (int)floorf(yc);
        int xl = (int)floorf(xc);
        int yh = min(yl + 1, HH - 1);
        int xh = min(xl + 1, WW - 1);
        float ly = yc - (float)yl;
        float lx = xc - (float)xl;
        float v00 = base[((size_t)yl * WW + xl) * CC + c];
        float v01 = base[((size_t)yl * WW + xh) * CC + c];
        float v10 = base[((size_t)yh * WW + xl) * CC + c];
        float v11 = base[((size_t)yh * WW + xh) * CC + c];
        float v = v00 * (1.f - ly) * (1.f - lx) + v01 * (1.f - ly) * lx +
                  v10 * ly * (1.f - lx) + v11 * ly * lx;
        acc += m ? v : 0.f;
    }
    acc *= 0.25f;
    g_roisem[((size_t)k * PP + p) * CC + c] = acc;
    float bn = acc * g_sc_sem[c] + g_sh_sem[c];
    g_bnsem[((size_t)k * CC + c) * PP + p] = fmaxf(bn, 0.f);
}

// ---------------- fused dual 3x3 conv (256 -> 64) ----------------
__global__ __launch_bounds__(224)
void k_conv(const float* __restrict__ bias_sem, const float* __restrict__ bias_fpn) {
    int k = blockIdx.x;
    int ocg = blockIdx.y;   // 0 or 1 -> 32 oc each
    __shared__ __align__(16) float tS[4][16][16];
    __shared__ __align__(16) float tF[4][16][16];
    __shared__ __align__(16) float wS[4][9][32];
    __shared__ __align__(16) float wF[4][9][32];
    int tid = threadIdx.x;
    // zero padded tiles once (borders never rewritten)
    for (int i = tid; i < 4 * 256; i += 224) {
        ((float*)tS)[i] = 0.f;
        ((float*)tF)[i] = 0.f;
    }
    float acc[32];
#pragma unroll
    for (int o = 0; o < 32; o++) acc[o] = 0.f;
    int p = tid;
    int y = p / OSZ, x = p % OSZ;
    const float* bs = g_bnsem + (size_t)k * CC * PP;
    const float* bf = g_bnfpn + (size_t)k * CC * PP;
    __syncthreads();
    for (int c0 = 0; c0 < CC; c0 += 4) {
        for (int i = tid; i < 4 * PP; i += 224) {
            int icc = i / PP, pp = i % PP;
            int yy = pp / OSZ, xx = pp % OSZ;
            tS[icc][yy + 1][xx + 1] = bs[(c0 + icc) * PP + pp];
            tF[icc][yy + 1][xx + 1] = bf[(c0 + icc) * PP + pp];
        }
        for (int i = tid; i < 4 * 9 * 32; i += 224) {
            int icc = i / 288, r = i % 288, tap = r / 32, oc = r % 32;
            wS[icc][tap][oc] = g_wsemT[(c0 + icc) * 576 + tap * 64 + ocg * 32 + oc];
            wF[icc][tap][oc] = g_wfpnT[(c0 + icc) * 576 + tap * 64 + ocg * 32 + oc];
        }
        __syncthreads();
        if (p < PP) {
#pragma unroll 1
            for (int icc = 0; icc < 4; icc++) {
                float ps[9], pf[9];
#pragma unroll
                for (int dy = 0; dy < 3; dy++)
#pragma unroll
                    for (int dx = 0; dx < 3; dx++) {
                        ps[dy * 3 + dx] = tS[icc][y + dy][x + dx];
                        pf[dy * 3 + dx] = tF[icc][y + dy][x + dx];
                    }
#pragma unroll
                for (int og = 0; og < 8; og++) {
#pragma unroll
                    for (int tap = 0; tap < 9; tap++) {
                        float4 w4 = *(const float4*)&wS[icc][tap][og * 4];
                        acc[og * 4 + 0] += ps[tap] * w4.x;
                        acc[og * 4 + 1] += ps[tap] * w4.y;
                        acc[og * 4 + 2] += ps[tap] * w4.z;
                        acc[og * 4 + 3] += ps[tap] * w4.w;
                        float4 v4 = *(const float4*)&wF[icc][tap][og * 4];
                        acc[og * 4 + 0] += pf[tap] * v4.x;
                        acc[og * 4 + 1] += pf[tap] * v4.y;
                        acc[og * 4 + 2] += pf[tap] * v4.z;
                        acc[og * 4 + 3] += pf[tap] * v4.w;
                    }
                }
            }
        }
        __syncthreads();
    }
    if (p < PP) {
#pragma unroll
        for (int o = 0; o < 32; o++) {
            int oc = ocg * 32 + o;
            g_abuf[((size_t)k * 64 + oc) * PP + p] = acc[o] + bias_sem[oc] + bias_fpn[oc];
        }
    }
}

// ---------------- bn_relu(a) + 1x1 conv(64->196) + sigmoid ----------------
// block (k, half): half covers 98 positions. Static smem only (~25.6 KB).
__global__ __launch_bounds__(128)
void k_aff(const float* __restrict__ aff_b) {
    __shared__ float sAr[64][100];     // 98 + pad
    int k = blockIdx.x;
    int half = blockIdx.y;
    int p0 = half * 98;
    int tid = threadIdx.x;
    for (int i = tid; i < 64 * 98; i += 128) {
        int c = i / 98, pp = i % 98;
        float v = g_abuf[((size_t)k * 64 + c) * PP + p0 + pp];
        sAr[c][pp] = fmaxf(v * g_sc_aff[c] + g_sh_aff[c], 0.f);
    }
    __syncthreads();
    int p = tid;
    if (p < 98) {
        for (int ng = 0; ng < 49; ng++) {
            float4 acc;
            acc.x = __ldg(&aff_b[ng * 4 + 0]);
            acc.y = __ldg(&aff_b[ng * 4 + 1]);
            acc.z = __ldg(&aff_b[ng * 4 + 2]);
            acc.w = __ldg(&aff_b[ng * 4 + 3]);
#pragma unroll 8
            for (int c = 0; c < 64; c++) {
                float av = sAr[c][p];
                float4 w4 = __ldg((const float4*)&g_waffT[c * PP + ng * 4]);
                acc.x += av * w4.x;
                acc.y += av * w4.y;
                acc.z += av * w4.z;
                acc.w += av * w4.w;
            }
            float* Ao = g_Abuf + ((size_t)k * PP + ng * 4) * PP + p0 + p;
            Ao[0 * PP] = 1.f / (1.f + expf(-acc.x));
            Ao[1 * PP] = 1.f / (1.f + expf(-acc.y));
            Ao[2 * PP] = 1.f / (1.f + expf(-acc.z));
            Ao[3 * PP] = 1.f / (1.f + expf(-acc.w));
        }
    }
}

// ---------------- degree / dis ----------------
__global__ __launch_bounds__(224)
void k_deg() {
    int k = blockIdx.x;
    int j = threadIdx.x;
    if (j >= PP) return;
    const float* A = g_Abuf + (size_t)k * PP * PP;
    float s = 0.f;
    for (int i = 0; i < PP; i++) s += A[i * PP + j];
    g_dis[k * PP + j] = rsqrtf(s);
}

// ---------------- xw1s = dis_i * (X @ w1) ----------------
__global__ __launch_bounds__(224)
void k_xw1(const float* __restrict__ rf, const float* __restrict__ w1) {
    __shared__ __align__(16) float sW1[CC * 16];
    int k = blockIdx.x;
    int tid = threadIdx.x;
    for (int i = tid; i < CC * 16; i += 224) sW1[i] = w1[i];
    __syncthreads();
    int i = tid;
    if (i >= PP) return;
    float acc[16];
#pragma unroll
    for (int f = 0; f < 16; f++) acc[f] = 0.f;
    const float* x = rf + (size_t)k * CC * PP;
    for (int c = 0; c < CC; c++) {
        float v = x[c * PP + i];
#pragma unroll
        for (int fg = 0; fg < 4; fg++) {
            float4 w4 = *(const float4*)&sW1[c * 16 + fg * 4];
            acc[fg * 4 + 0] += v * w4.x;
            acc[fg * 4 + 1] += v * w4.y;
            acc[fg * 4 + 2] += v * w4.z;
            acc[fg * 4 + 3] += v * w4.w;
        }
    }
    float di = g_dis[k * PP + i];
    float* o = g_xw1 + ((size_t)k * PP + i) * 16;
#pragma unroll
    for (int fg = 0; fg < 4; fg++) {
        float4 v;
        v.x = di * acc[fg * 4 + 0];
        v.y = di * acc[fg * 4 + 1];
        v.z = di * acc[fg * 4 + 2];
        v.w = di * acc[fg * 4 + 3];
        *(float4*)&o[fg * 4] = v;
    }
}

// ---------------- agg1 + relu + (x1 @ w2) scaled ----------------
__global__ __launch_bounds__(224)
void k_gcn1(const float* __restrict__ b1, const float* __restrict__ w2) {
    __shared__ __align__(16) float sXW[PP * 16];
    __shared__ __align__(16) float sW2[16 * CC];
    int k = blockIdx.x;
    int tid = threadIdx.x;
    for (int i = tid; i < PP * 16; i += 224) sXW[i] = g_xw1[(size_t)k * PP * 16 + i];
    for (int i = tid; i < 16 * CC; i += 224) sW2[i] = w2[i];
    __syncthreads();
    int j = tid;
    if (j >= PP) return;
    float acc[16];
#pragma unroll
    for (int f = 0; f < 16; f++) acc[f] = 0.f;
    const float* A = g_Abuf + (size_t)k * PP * PP;
    for (int i = 0; i < PP; i++) {
        float a = A[i * PP + j];
#pragma unroll
        for (int fg = 0; fg < 4; fg++) {
            float4 xv = *(const float4*)&sXW[i * 16 + fg * 4];
            acc[fg * 4 + 0] += a * xv.x;
            acc[fg * 4 + 1] += a * xv.y;
            acc[fg * 4 + 2] += a * xv.z;
            acc[fg * 4 + 3] += a * xv.w;
        }
    }
    float dj = g_dis[k * PP + j];
    float x1[16];
#pragma unroll
    for (int f = 0; f < 16; f++) x1[f] = fmaxf(acc[f] * dj + b1[f], 0.f);
    float* o = g_xw2 + ((size_t)k * PP + j) * CC;
    for (int g = 0; g < 64; g++) {
        float4 s = make_float4(0.f, 0.f, 0.f, 0.f);
#pragma unroll
        for (int f = 0; f < 16; f++) {
            float4 w4 = *(const float4*)&sW2[f * CC + g * 4];
            s.x += x1[f] * w4.x;
            s.y += x1[f] * w4.y;
            s.z += x1[f] * w4.z;
            s.w += x1[f] * w4.w;
        }
        s.x *= dj; s.y *= dj; s.z *= dj; s.w *= dj;
        *(float4*)&o[g * 4] = s;
    }
}

// ---------------- agg2 + bias + add roi_sem -> out ----------------
__global__ __launch_bounds__(224)
void k_gcn2(const float* __restrict__ b2, float* __restrict__ out) {
    __shared__ __align__(16) float sX2[PP * 32];
    int fc = blockIdx.x;          // 0..7 (32 f each)
    int k = blockIdx.y;
    int f0 = fc * 32;
    int tid = threadIdx.x;
    for (int i = tid; i < PP * 32; i += 224) {
        int ii = i / 32, f = i % 32;
        sX2[i] = g_xw2[((size_t)k * PP + ii) * CC + f0 + f];
    }
    __syncthreads();
    int j = tid;
    if (j >= PP) return;
    float acc[32];
#pragma unroll
    for (int f = 0; f < 32; f++) acc[f] = 0.f;
    const float* A = g_Abuf + (size_t)k * PP * PP;
    for (int i = 0; i < PP; i++) {
        float a = A[i * PP + j];
#pragma unroll
        for (int fg = 0; fg < 8; fg++) {
            float4 xv = *(const float4*)&sX2[i * 32 + fg * 4];
            acc[fg * 4 + 0] += a * xv.x;
            acc[fg * 4 + 1] += a * xv.y;
            acc[fg * 4 + 2] += a * xv.z;
            acc[fg * 4 + 3] += a * xv.w;
        }
    }
    float dj = g_dis[k * PP + j];
    const float* rs = g_roisem + ((size_t)k * PP + j) * CC;
#pragma unroll
    for (int f = 0; f < 32; f++) {
        int fo = f0 + f;
        out[((size_t)k * CC + fo) * PP + j] = rs[fo] + dj * acc[f] + b2[fo];
    }
}

// ---------------- launch ----------------
extern "C" void kernel_launch(void* const* d_in, const int* in_sizes, int n_in,
                              void* d_out, int out_size) {
    const float* roi_feature = (const float*)d_in[0];
    const float* semantic = (const float*)d_in[1];
    const float* boxes = (const float*)d_in[2];
    const float* bn_sem_g = (const float*)d_in[3];
    const float* bn_sem_b = (const float*)d_in[4];
    const float* bn_sem_m = (const float*)d_in[5];
    const float* bn_sem_v = (const float*)d_in[6];
    const float* conv_sem_w = (const float*)d_in[7];
    const float* conv_sem_b = (const float*)d_in[8];
    const float* bn_fpn_g = (const float*)d_in[9];
    const float* bn_fpn_b = (const float*)d_in[10];
    const float* bn_fpn_m = (const float*)d_in[11];
    const float* bn_fpn_v = (const float*)d_in[12];
    const float* conv_fpn_w = (const float*)d_in[13];
    const float* conv_fpn_b = (const float*)d_in[14];
    const float* bn_aff_g = (const float*)d_in[15];
    const float* bn_aff_b = (const float*)d_in[16];
    const float* bn_aff_m = (const float*)d_in[17];
    const float* bn_aff_v = (const float*)d_in[18];
    const float* conv_aff_w = (const float*)d_in[19];
    const float* conv_aff_b = (const float*)d_in[20];
    const float* gcn1_w = (const float*)d_in[21];
    const float* gcn1_b = (const float*)d_in[22];
    const float* gcn2_w = (const float*)d_in[23];
    const float* gcn2_b = (const float*)d_in[24];
    float* out = (float*)d_out;

    k_prep_scale<<<1, 256>>>(bn_sem_g, bn_sem_b, bn_sem_m, bn_sem_v,
                             bn_fpn_g, bn_fpn_b, bn_fpn_m, bn_fpn_v,
                             bn_aff_g, bn_aff_b, bn_aff_m, bn_aff_v);
    k_prep_wt<<<302, 256>>>(conv_sem_w, conv_fpn_w, conv_aff_w);
    {
        dim3 g(HWSZ / 32, CC / 32, BB);
        dim3 b(32, 8);
        k_trans_sem<<<g, b>>>(semantic);
    }
    k_bnfpn<<<(KK * CC * PP + 255) / 256, 256>>>(roi_feature);
    {
        dim3 g(PP, KK);
        k_roialign<<<g, 256>>>(boxes);
    }
    {
        dim3 g(KK, 2);
        k_conv<<<g, 224>>>(conv_sem_b, conv_fpn_b);
    }
    {
        dim3 g(KK, 2);
        k_aff<<<g, 128>>>(conv_aff_b);
    }
    k_deg<<<KK, 224>>>();
    k_xw1<<<KK, 224>>>(roi_feature, gcn1_w);
    k_gcn1<<<KK, 224>>>(gcn1_b, gcn2_w);
    {
        dim3 g(8, KK);
        k_gcn2<<<g, 224>>>(gcn2_b, out);
    }
}

// round 4
// speedup vs baseline: 2.0503x; 2.0503x over previous
#include <cuda_runtime.h>
#include <math.h>

#define KK 256
#define CC 256
#define PP 196
#define OSZ 14
#define HH 112
#define WW 112
#define BB 4
#define HWSZ 12544

// conv-mma geometry
#define ICC 32                 // ic chunk
#define ACT_STR 297            // padded position stride (mod 32 == 9)
#define GUARD 17               // guard cells before ppad 0
#define BSTR 72                // B smem stride (mod 32 == 8)
#define ACT_FLOATS (2 * ICC * ACT_STR)   // 19008
#define B_FLOATS (2 * ICC * BSTR)        // 4608
#define CONV_SMEM ((ACT_FLOATS + B_FLOATS) * 4)
#define OUT_STR 264

// ---------------- scratch ----------------
__device__ float g_semT[BB * HWSZ * CC];      // semantic NHWC
__device__ float g_roisem[KK * PP * CC];      // roi_sem NHWC [k][p][c]
__device__ float g_abuf[KK * 64 * PP];        // conv sum 'a' NCHW
__device__ float g_Abuf[KK * PP * PP];        // sigmoid affinity A[k][i][j]
__device__ float g_dis[KK * PP];              // rsqrt(deg)
__device__ float g_xw1[KK * PP * 16];
__device__ float g_xw2[KK * PP * CC];
__device__ float g_wsemT[CC * 9 * 64];        // w [ic][tap][oc]
__device__ float g_wfpnT[CC * 9 * 64];
__device__ float g_waffT[64 * PP];
__device__ float g_sc_sem[CC], g_sh_sem[CC];
__device__ float g_sc_fpn[CC], g_sh_fpn[CC];
__device__ float g_sc_aff[64], g_sh_aff[64];

__device__ __forceinline__ float cvt_tf32(float x) {
    unsigned r;
    asm("cvt.rna.tf32.f32 %0, %1;" : "=r"(r) : "f"(x));
    return __uint_as_float(r);
}

__device__ __forceinline__ void mma_tf32(float* c, const unsigned* a, const unsigned* b) {
    asm volatile(
        "mma.sync.aligned.m16n8k8.row.col.f32.tf32.tf32.f32 "
        "{%0,%1,%2,%3}, {%4,%5,%6,%7}, {%8,%9}, {%0,%1,%2,%3};"
        : "+f"(c[0]), "+f"(c[1]), "+f"(c[2]), "+f"(c[3])
        : "r"(a[0]), "r"(a[1]), "r"(a[2]), "r"(a[3]), "r"(b[0]), "r"(b[1]));
}

// ---------------- prep: bn scale/shift ----------------
__global__ void k_prep_scale(const float* gs, const float* bs, const float* ms, const float* vs,
                             const float* gf, const float* bf, const float* mf, const float* vf,
                             const float* ga, const float* ba, const float* ma, const float* va) {
    int t = threadIdx.x;
    if (t < CC) {
        float s = gs[t] * rsqrtf(vs[t] + 1e-5f);
        g_sc_sem[t] = s;
        g_sh_sem[t] = bs[t] - ms[t] * s;
        float f = gf[t] * rsqrtf(vf[t] + 1e-5f);
        g_sc_fpn[t] = f;
        g_sh_fpn[t] = bf[t] - mf[t] * f;
    }
    if (t < 64) {
        float a = ga[t] * rsqrtf(va[t] + 1e-5f);
        g_sc_aff[t] = a;
        g_sh_aff[t] = ba[t] - ma[t] * a;
    }
}

// ---------------- prep: weight transposes ----------------
__global__ void k_prep_wt(const float* wsem, const float* wfpn, const float* waff) {
    const int N1 = CC * 9 * 64;
    const int NA = 64 * PP;
    int total = 2 * N1 + NA;
    for (int d = blockIdx.x * blockDim.x + threadIdx.x; d < total; d += gridDim.x * blockDim.x) {
        if (d < N1) {
            int ic = d / 576, r = d % 576, tap = r / 64, oc = r % 64;
            g_wsemT[d] = wsem[oc * (CC * 9) + ic * 9 + tap];
        } else if (d < 2 * N1) {
            int e = d - N1;
            int ic = e / 576, r = e % 576, tap = r / 64, oc = r % 64;
            g_wfpnT[e] = wfpn[oc * (CC * 9) + ic * 9 + tap];
        } else {
            int e = d - 2 * N1;
            int c = e / PP, n = e % PP;
            g_waffT[e] = waff[n * 64 + c];
        }
    }
}

// ---------------- transpose semantic NCHW -> NHWC ----------------
__global__ void k_trans_sem(const float* __restrict__ sem) {
    __shared__ float tile[32][33];
    int b = blockIdx.z;
    int hw0 = blockIdx.x * 32;
    int c0 = blockIdx.y * 32;
    int tx = threadIdx.x, ty = threadIdx.y;
    const float* src = sem + (size_t)b * CC * HWSZ;
    float* dst = g_semT + (size_t)b * HWSZ * CC;
#pragma unroll
    for (int yy = 0; yy < 32; yy += 8)
        tile[ty + yy][tx] = src[(size_t)(c0 + ty + yy) * HWSZ + hw0 + tx];
    __syncthreads();
#pragma unroll
    for (int yy = 0; yy < 32; yy += 8)
        dst[(size_t)(hw0 + ty + yy) * CC + c0 + tx] = tile[tx][ty + yy];
}

// ---------------- ROI align (NHWC out only) ----------------
__global__ void k_roialign(const float* __restrict__ boxes) {
    int p = blockIdx.x;
    int k = blockIdx.y;
    int c = threadIdx.x;
    int bidx = (int)boxes[k * 5 + 0];
    float x1 = boxes[k * 5 + 1], y1 = boxes[k * 5 + 2];
    float x2 = boxes[k * 5 + 3], y2 = boxes[k * 5 + 4];
    float bw = fmaxf(x2 - x1, 1.f) * (1.f / OSZ);
    float bh = fmaxf(y2 - y1, 1.f) * (1.f / OSZ);
    int oy = p / OSZ, ox = p % OSZ;
    const float* base = g_semT + (size_t)bidx * HWSZ * CC;
    float acc = 0.f;
#pragma unroll
    for (int s = 0; s < 4; s++) {
        int sy = oy * 2 + (s >> 1);
        int sx = ox * 2 + (s & 1);
        float yv = y1 + bh * ((sy + 0.5f) * 0.5f);
        float xv = x1 + bw * ((sx + 0.5f) * 0.5f);
        bool m = (yv >= -1.f) && (yv <= (float)HH) && (xv >= -1.f) && (xv <= (float)WW);
        float yc = fminf(fmaxf(yv, 0.f), (float)(HH - 1));
        float xc = fminf(fmaxf(xv, 0.f), (float)(WW - 1));
        int yl = (int)floorf(yc);
        int xl = (int)floorf(xc);
        int yh = min(yl + 1, HH - 1);
        int xh = min(xl + 1, WW - 1);
        float ly = yc - (float)yl;
        float lx = xc - (float)xl;
        float v00 = base[((size_t)yl * WW + xl) * CC + c];
        float v01 = base[((size_t)yl * WW + xh) * CC + c];
        float v10 = base[((size_t)yh * WW + xl) * CC + c];
        float v11 = base[((size_t)yh * WW + xh) * CC + c];
        float v = v00 * (1.f - ly) * (1.f - lx) + v01 * (1.f - ly) * lx +
                  v10 * ly * (1.f - lx) + v11 * ly * lx;
        acc += m ? v : 0.f;
    }
    acc *= 0.25f;
    g_roisem[((size_t)k * PP + p) * CC + c] = acc;
}

// ---------------- tf32 tensor-core dual 3x3 conv (256 -> 64, fused BN+ReLU) ----------------
// CTA = one ROI. M = 256 padded positions (16x16 grid, zero guards), N = 64 oc,
// K = 2 branches x 9 taps x 256 ic, chunked by 32 ic. Taps are address shifts dy*16+dx.
__global__ __launch_bounds__(256, 2)
void k_conv_mma(const float* __restrict__ roi_feature,
                const float* __restrict__ bias_sem, const float* __restrict__ bias_fpn) {
    extern __shared__ float dyn[];
    float* act = dyn;                    // [2][ICC][ACT_STR]
    float* Bsm = dyn + ACT_FLOATS;       // [2 buf][ICC][BSTR]
    int k = blockIdx.x;
    int tid = threadIdx.x;
    int warp = tid >> 5;
    int lane = tid & 31;
    int g = lane >> 2;
    int t = lane & 3;
    int wrow = warp * 32;

    float acc[2][8][4];
#pragma unroll
    for (int mg = 0; mg < 2; mg++)
#pragma unroll
        for (int n8 = 0; n8 < 8; n8++)
#pragma unroll
            for (int q = 0; q < 4; q++) acc[mg][n8][q] = 0.f;

    const float* rfk = roi_feature + (size_t)k * CC * PP;
    const float* rsk = g_roisem + (size_t)k * PP * CC;

    // B stage helper data
    int brow = tid >> 3;              // 0..31 (ic within chunk)
    int bcol = (tid & 7) * 8;         // oc

    for (int ic0 = 0; ic0 < CC; ic0 += ICC) {
        // ---- stage activations ----
        for (int i = tid; i < ACT_FLOATS; i += 256) act[i] = 0.f;
        __syncthreads();
        // sem branch (br 0): lanes over channels (coalesced on NHWC)
        for (int i = tid; i < PP * ICC; i += 256) {
            int p = i >> 5, icc = i & 31;
            int c = ic0 + icc;
            float v = rsk[(size_t)p * CC + c];
            v = fmaxf(v * g_sc_sem[c] + g_sh_sem[c], 0.f);
            act[icc * ACT_STR + GUARD + (p / OSZ) * 16 + (p % OSZ)] = cvt_tf32(v);
        }
        // fpn branch (br 1): lanes over positions (coalesced on NCHW)
        for (int i = tid; i < ICC * PP; i += 256) {
            int icc = i / PP, p = i % PP;
            int c = ic0 + icc;
            float v = rfk[(size_t)c * PP + p];
            v = fmaxf(v * g_sc_fpn[c] + g_sh_fpn[c], 0.f);
            act[(ICC + icc) * ACT_STR + GUARD + (p / OSZ) * 16 + (p % OSZ)] = cvt_tf32(v);
        }
        // stage first B tile (br0, tap0) into buf 0
        {
            const float* w = g_wsemT + (size_t)(ic0 + brow) * 576 + 0 * 64 + bcol;
            float4 a4 = *(const float4*)w;
            float4 b4 = *(const float4*)(w + 4);
            float* d = Bsm + brow * BSTR + bcol;
            d[0] = cvt_tf32(a4.x); d[1] = cvt_tf32(a4.y); d[2] = cvt_tf32(a4.z); d[3] = cvt_tf32(a4.w);
            d[4] = cvt_tf32(b4.x); d[5] = cvt_tf32(b4.y); d[6] = cvt_tf32(b4.z); d[7] = cvt_tf32(b4.w);
        }
        __syncthreads();

        int cur = 0;
        for (int idx = 0; idx < 18; idx++) {
            int br = idx / 9, tap = idx % 9;
            int off = (tap / 3 - 1) * 16 + (tap % 3 - 1);
            // prefetch next B into regs (overlaps with mma loop)
            float4 pa, pb;
            if (idx < 17) {
                int nbr = (idx + 1) / 9, ntap = (idx + 1) % 9;
                const float* wT = nbr ? g_wfpnT : g_wsemT;
                const float* w = wT + (size_t)(ic0 + brow) * 576 + ntap * 64 + bcol;
                pa = *(const float4*)w;
                pb = *(const float4*)(w + 4);
            }
            const float* actb = act + br * (ICC * ACT_STR);
            const float* Bc = Bsm + cur * (ICC * BSTR);
#pragma unroll
            for (int ks = 0; ks < 4; ks++) {
                unsigned bf[8][2];
#pragma unroll
                for (int n8 = 0; n8 < 8; n8++) {
                    bf[n8][0] = __float_as_uint(Bc[(ks * 8 + t) * BSTR + n8 * 8 + g]);
                    bf[n8][1] = __float_as_uint(Bc[(ks * 8 + t + 4) * BSTR + n8 * 8 + g]);
                }
                unsigned af[2][4];
#pragma unroll
                for (int mg = 0; mg < 2; mg++) {
                    int r0 = GUARD + wrow + mg * 16 + g + off;
                    const float* a0 = actb + (ks * 8 + t) * ACT_STR + r0;
                    const float* a1 = actb + (ks * 8 + t + 4) * ACT_STR + r0;
                    af[mg][0] = __float_as_uint(a0[0]);
                    af[mg][1] = __float_as_uint(a0[8]);
                    af[mg][2] = __float_as_uint(a1[0]);
                    af[mg][3] = __float_as_uint(a1[8]);
                }
#pragma unroll
                for (int mg = 0; mg < 2; mg++)
#pragma unroll
                    for (int n8 = 0; n8 < 8; n8++)
                        mma_tf32(acc[mg][n8], af[mg], bf[n8]);
            }
            __syncthreads();
            if (idx < 17) {
                float* d = Bsm + (cur ^ 1) * (ICC * BSTR) + brow * BSTR + bcol;
                d[0] = cvt_tf32(pa.x); d[1] = cvt_tf32(pa.y); d[2] = cvt_tf32(pa.z); d[3] = cvt_tf32(pa.w);
                d[4] = cvt_tf32(pb.x); d[5] = cvt_tf32(pb.y); d[6] = cvt_tf32(pb.z); d[7] = cvt_tf32(pb.w);
            }
            __syncthreads();
            cur ^= 1;
        }
    }

    // ---- epilogue: frags -> smem [oc][ppad] -> g_abuf NCHW ----
    float* outsm = act;   // reuse (64 * OUT_STR = 16896 <= 19008)
#pragma unroll
    for (int mg = 0; mg < 2; mg++) {
        int r0 = wrow + mg * 16 + g;
#pragma unroll
        for (int n8 = 0; n8 < 8; n8++) {
            int oc = n8 * 8 + 2 * t;
            outsm[oc * OUT_STR + r0] = acc[mg][n8][0];
            outsm[(oc + 1) * OUT_STR + r0] = acc[mg][n8][1];
            outsm[oc * OUT_STR + r0 + 8] = acc[mg][n8][2];
            outsm[(oc + 1) * OUT_STR + r0 + 8] = acc[mg][n8][3];
        }
    }
    __syncthreads();
    for (int i = tid; i < 64 * PP; i += 256) {
        int oc = i / PP, p = i % PP;
        float v = outsm[oc * OUT_STR + (p / OSZ) * 16 + (p % OSZ)];
        g_abuf[((size_t)k * 64 + oc) * PP + p] = v + __ldg(&bias_sem[oc]) + __ldg(&bias_fpn[oc]);
    }
}

// ---------------- bn_relu(a) + 1x1 conv(64->196) + sigmoid ----------------
__global__ __launch_bounds__(128)
void k_aff(const float* __restrict__ aff_b) {
    __shared__ float sAr[64][100];
    int k = blockIdx.x;
    int half = blockIdx.y;
    int p0 = half * 98;
    int tid = threadIdx.x;
    for (int i = tid; i < 64 * 98; i += 128) {
        int c = i / 98, pp = i % 98;
        float v = g_abuf[((size_t)k * 64 + c) * PP + p0 + pp];
        sAr[c][pp] = fmaxf(v * g_sc_aff[c] + g_sh_aff[c], 0.f);
    }
    __syncthreads();
    int p = tid;
    if (p < 98) {
        for (int ng = 0; ng < 49; ng++) {
            float4 acc;
            acc.x = __ldg(&aff_b[ng * 4 + 0]);
            acc.y = __ldg(&aff_b[ng * 4 + 1]);
            acc.z = __ldg(&aff_b[ng * 4 + 2]);
            acc.w = __ldg(&aff_b[ng * 4 + 3]);
#pragma unroll 8
            for (int c = 0; c < 64; c++) {
                float av = sAr[c][p];
                float4 w4 = __ldg((const float4*)&g_waffT[c * PP + ng * 4]);
                acc.x += av * w4.x;
                acc.y += av * w4.y;
                acc.z += av * w4.z;
                acc.w += av * w4.w;
            }
            float* Ao = g_Abuf + ((size_t)k * PP + ng * 4) * PP + p0 + p;
            Ao[0 * PP] = 1.f / (1.f + expf(-acc.x));
            Ao[1 * PP] = 1.f / (1.f + expf(-acc.y));
            Ao[2 * PP] = 1.f / (1.f + expf(-acc.z));
            Ao[3 * PP] = 1.f / (1.f + expf(-acc.w));
        }
    }
}

// ---------------- degree / dis ----------------
__global__ __launch_bounds__(224)
void k_deg() {
    int k = blockIdx.x;
    int j = threadIdx.x;
    if (j >= PP) return;
    const float* A = g_Abuf + (size_t)k * PP * PP;
    float s = 0.f;
    for (int i = 0; i < PP; i++) s += A[i * PP + j];
    g_dis[k * PP + j] = rsqrtf(s);
}

// ---------------- xw1s ----------------
__global__ __launch_bounds__(224)
void k_xw1(const float* __restrict__ rf, const float* __restrict__ w1) {
    __shared__ __align__(16) float sW1[CC * 16];
    int k = blockIdx.x;
    int tid = threadIdx.x;
    for (int i = tid; i < CC * 16; i += 224) sW1[i] = w1[i];
    __syncthreads();
    int i = tid;
    if (i >= PP) return;
    float acc[16];
#pragma unroll
    for (int f = 0; f < 16; f++) acc[f] = 0.f;
    const float* x = rf + (size_t)k * CC * PP;
    for (int c = 0; c < CC; c++) {
        float v = x[c * PP + i];
#pragma unroll
        for (int fg = 0; fg < 4; fg++) {
            float4 w4 = *(const float4*)&sW1[c * 16 + fg * 4];
            acc[fg * 4 + 0] += v * w4.x;
            acc[fg * 4 + 1] += v * w4.y;
            acc[fg * 4 + 2] += v * w4.z;
            acc[fg * 4 + 3] += v * w4.w;
        }
    }
    float di = g_dis[k * PP + i];
    float* o = g_xw1 + ((size_t)k * PP + i) * 16;
#pragma unroll
    for (int fg = 0; fg < 4; fg++) {
        float4 v;
        v.x = di * acc[fg * 4 + 0];
        v.y = di * acc[fg * 4 + 1];
        v.z = di * acc[fg * 4 + 2];
        v.w = di * acc[fg * 4 + 3];
        *(float4*)&o[fg * 4] = v;
    }
}

// ---------------- agg1 + relu + (x1 @ w2) scaled ----------------
__global__ __launch_bounds__(224)
void k_gcn1(const float* __restrict__ b1, const float* __restrict__ w2) {
    __shared__ __align__(16) float sXW[PP * 16];
    __shared__ __align__(16) float sW2[16 * CC];
    int k = blockIdx.x;
    int tid = threadIdx.x;
    for (int i = tid; i < PP * 16; i += 224) sXW[i] = g_xw1[(size_t)k * PP * 16 + i];
    for (int i = tid; i < 16 * CC; i += 224) sW2[i] = w2[i];
    __syncthreads();
    int j = tid;
    if (j >= PP) return;
    float acc[16];
#pragma unroll
    for (int f = 0; f < 16; f++) acc[f] = 0.f;
    const float* A = g_Abuf + (size_t)k * PP * PP;
    for (int i = 0; i < PP; i++) {
        float a = A[i * PP + j];
#pragma unroll
        for (int fg = 0; fg < 4; fg++) {
            float4 xv = *(const float4*)&sXW[i * 16 + fg * 4];
            acc[fg * 4 + 0] += a * xv.x;
            acc[fg * 4 + 1] += a * xv.y;
            acc[fg * 4 + 2] += a * xv.z;
            acc[fg * 4 + 3] += a * xv.w;
        }
    }
    float dj = g_dis[k * PP + j];
    float x1[16];
#pragma unroll
    for (int f = 0; f < 16; f++) x1[f] = fmaxf(acc[f] * dj + b1[f], 0.f);
    float* o = g_xw2 + ((size_t)k * PP + j) * CC;
    for (int g = 0; g < 64; g++) {
        float4 s = make_float4(0.f, 0.f, 0.f, 0.f);
#pragma unroll
        for (int f = 0; f < 16; f++) {
            float4 w4 = *(const float4*)&sW2[f * CC + g * 4];
            s.x += x1[f] * w4.x;
            s.y += x1[f] * w4.y;
            s.z += x1[f] * w4.z;
            s.w += x1[f] * w4.w;
        }
        s.x *= dj; s.y *= dj; s.z *= dj; s.w *= dj;
        *(float4*)&o[g * 4] = s;
    }
}

// ---------------- agg2 + bias + add roi_sem -> out ----------------
__global__ __launch_bounds__(224)
void k_gcn2(const float* __restrict__ b2, float* __restrict__ out) {
    __shared__ __align__(16) float sX2[PP * 32];
    int fc = blockIdx.x;
    int k = blockIdx.y;
    int f0 = fc * 32;
    int tid = threadIdx.x;
    for (int i = tid; i < PP * 32; i += 224) {
        int ii = i / 32, f = i % 32;
        sX2[i] = g_xw2[((size_t)k * PP + ii) * CC + f0 + f];
    }
    __syncthreads();
    int j = tid;
    if (j >= PP) return;
    float acc[32];
#pragma unroll
    for (int f = 0; f < 32; f++) acc[f] = 0.f;
    const float* A = g_Abuf + (size_t)k * PP * PP;
    for (int i = 0; i < PP; i++) {
        float a = A[i * PP + j];
#pragma unroll
        for (int fg = 0; fg < 8; fg++) {
            float4 xv = *(const float4*)&sX2[i * 32 + fg * 4];
            acc[fg * 4 + 0] += a * xv.x;
            acc[fg * 4 + 1] += a * xv.y;
            acc[fg * 4 + 2] += a * xv.z;
            acc[fg * 4 + 3] += a * xv.w;
        }
    }
    float dj = g_dis[k * PP + j];
    const float* rs = g_roisem + ((size_t)k * PP + j) * CC;
#pragma unroll
    for (int f = 0; f < 32; f++) {
        int fo = f0 + f;
        out[((size_t)k * CC + fo) * PP + j] = rs[fo] + dj * acc[f] + b2[fo];
    }
}

// ---------------- launch ----------------
extern "C" void kernel_launch(void* const* d_in, const int* in_sizes, int n_in,
                              void* d_out, int out_size) {
    const float* roi_feature = (const float*)d_in[0];
    const float* semantic = (const float*)d_in[1];
    const float* boxes = (const float*)d_in[2];
    const float* bn_sem_g = (const float*)d_in[3];
    const float* bn_sem_b = (const float*)d_in[4];
    const float* bn_sem_m = (const float*)d_in[5];
    const float* bn_sem_v = (const float*)d_in[6];
    const float* conv_sem_w = (const float*)d_in[7];
    const float* conv_sem_b = (const float*)d_in[8];
    const float* bn_fpn_g = (const float*)d_in[9];
    const float* bn_fpn_b = (const float*)d_in[10];
    const float* bn_fpn_m = (const float*)d_in[11];
    const float* bn_fpn_v = (const float*)d_in[12];
    const float* conv_fpn_w = (const float*)d_in[13];
    const float* conv_fpn_b = (const float*)d_in[14];
    const float* bn_aff_g = (const float*)d_in[15];
    const float* bn_aff_b = (const float*)d_in[16];
    const float* bn_aff_m = (const float*)d_in[17];
    const float* bn_aff_v = (const float*)d_in[18];
    const float* conv_aff_w = (const float*)d_in[19];
    const float* conv_aff_b = (const float*)d_in[20];
    const float* gcn1_w = (const float*)d_in[21];
    const float* gcn1_b = (const float*)d_in[22];
    const float* gcn2_w = (const float*)d_in[23];
    const float* gcn2_b = (const float*)d_in[24];
    float* out = (float*)d_out;

    static int smem_set = 0;
    if (!smem_set) {
        cudaFuncSetAttribute(k_conv_mma, cudaFuncAttributeMaxDynamicSharedMemorySize, CONV_SMEM);
        smem_set = 1;
    }

    k_prep_scale<<<1, 256>>>(bn_sem_g, bn_sem_b, bn_sem_m, bn_sem_v,
                             bn_fpn_g, bn_fpn_b, bn_fpn_m, bn_fpn_v,
                             bn_aff_g, bn_aff_b, bn_aff_m, bn_aff_v);
    k_prep_wt<<<302, 256>>>(conv_sem_w, conv_fpn_w, conv_aff_w);
    {
        dim3 g(HWSZ / 32, CC / 32, BB);
        dim3 b(32, 8);
        k_trans_sem<<<g, b>>>(semantic);
    }
    {
        dim3 g(PP, KK);
        k_roialign<<<g, 256>>>(boxes);
    }
    k_conv_mma<<<KK, 256, CONV_SMEM>>>(roi_feature, conv_sem_b, conv_fpn_b);
    {
        dim3 g(KK, 2);
        k_aff<<<g, 128>>>(conv_aff_b);
    }
    k_deg<<<KK, 224>>>();
    k_xw1<<<KK, 224>>>(roi_feature, gcn1_w);
    k_gcn1<<<KK, 224>>>(gcn1_b, gcn2_w);
    {
        dim3 g(8, KK);
        k_gcn2<<<g, 224>>>(gcn2_b, out);
    }
}

// round 5
// speedup vs baseline: 2.3821x; 1.1618x over previous
#include <cuda_runtime.h>
#include <math.h>

#define KK 256
#define CC 256
#define PP 196
#define OSZ 14
#define HH 112
#define WW 112
#define BB 4
#define HWSZ 12544

// conv-mma geometry
#define ICC 32
#define ACT_STR 297
#define GUARD 17
#define BSTR 72
#define ACT_FLOATS (2 * ICC * ACT_STR)
#define B_FLOATS (2 * ICC * BSTR)
#define CONV_SMEM ((ACT_FLOATS + B_FLOATS) * 4)
#define OUT_STR 264

// gcn2-mma geometry
#define G2_ASTR 232
#define G2_XSTR 72

// ---------------- scratch ----------------
__device__ float g_semT[BB * HWSZ * CC];
__device__ float g_roisem[KK * PP * CC];
__device__ float g_abuf[KK * 64 * PP];
__device__ float g_Abuf[KK * PP * PP];
__device__ float g_dis[KK * PP];
__device__ float g_xw1[KK * PP * 16];
__device__ float g_xw2[KK * PP * CC];
__device__ float g_wsemT[CC * 9 * 64];
__device__ float g_wfpnT[CC * 9 * 64];
__device__ float g_waffT[64 * PP];
__device__ int   g_tapoff[KK * PP * 16];
__device__ float g_tapw[KK * PP * 16];
__device__ float g_sc_sem[CC], g_sh_sem[CC];
__device__ float g_sc_fpn[CC], g_sh_fpn[CC];
__device__ float g_sc_aff[64], g_sh_aff[64];

__device__ __forceinline__ float cvt_tf32(float x) {
    unsigned r;
    asm("cvt.rna.tf32.f32 %0, %1;" : "=r"(r) : "f"(x));
    return __uint_as_float(r);
}

__device__ __forceinline__ void mma_tf32(float* c, const unsigned* a, const unsigned* b) {
    asm volatile(
        "mma.sync.aligned.m16n8k8.row.col.f32.tf32.tf32.f32 "
        "{%0,%1,%2,%3}, {%4,%5,%6,%7}, {%8,%9}, {%0,%1,%2,%3};"
        : "+f"(c[0]), "+f"(c[1]), "+f"(c[2]), "+f"(c[3])
        : "r"(a[0]), "r"(a[1]), "r"(a[2]), "r"(a[3]), "r"(b[0]), "r"(b[1]));
}

// ---------------- prep: bn scale/shift ----------------
__global__ void k_prep_scale(const float* gs, const float* bs, const float* ms, const float* vs,
                             const float* gf, const float* bf, const float* mf, const float* vf,
                             const float* ga, const float* ba, const float* ma, const float* va) {
    int t = threadIdx.x;
    if (t < CC) {
        float s = gs[t] * rsqrtf(vs[t] + 1e-5f);
        g_sc_sem[t] = s;
        g_sh_sem[t] = bs[t] - ms[t] * s;
        float f = gf[t] * rsqrtf(vf[t] + 1e-5f);
        g_sc_fpn[t] = f;
        g_sh_fpn[t] = bf[t] - mf[t] * f;
    }
    if (t < 64) {
        float a = ga[t] * rsqrtf(va[t] + 1e-5f);
        g_sc_aff[t] = a;
        g_sh_aff[t] = ba[t] - ma[t] * a;
    }
}

// ---------------- prep: weight transposes ----------------
__global__ void k_prep_wt(const float* wsem, const float* wfpn, const float* waff) {
    const int N1 = CC * 9 * 64;
    const int NA = 64 * PP;
    int total = 2 * N1 + NA;
    for (int d = blockIdx.x * blockDim.x + threadIdx.x; d < total; d += gridDim.x * blockDim.x) {
        if (d < N1) {
            int ic = d / 576, r = d % 576, tap = r / 64, oc = r % 64;
            g_wsemT[d] = wsem[oc * (CC * 9) + ic * 9 + tap];
        } else if (d < 2 * N1) {
            int e = d - N1;
            int ic = e / 576, r = e % 576, tap = r / 64, oc = r % 64;
            g_wfpnT[e] = wfpn[oc * (CC * 9) + ic * 9 + tap];
        } else {
            int e = d - 2 * N1;
            int c = e / PP, n = e % PP;
            g_waffT[e] = waff[n * 64 + c];
        }
    }
}

// ---------------- roi tap prep: one thread per (k, p) ----------------
__global__ void k_roiprep(const float* __restrict__ boxes) {
    int k = blockIdx.x;
    int p = threadIdx.x;
    if (p >= PP) return;
    int bidx = (int)boxes[k * 5 + 0];
    float x1 = boxes[k * 5 + 1], y1 = boxes[k * 5 + 2];
    float x2 = boxes[k * 5 + 3], y2 = boxes[k * 5 + 4];
    float bw = fmaxf(x2 - x1, 1.f) * (1.f / OSZ);
    float bh = fmaxf(y2 - y1, 1.f) * (1.f / OSZ);
    int oy = p / OSZ, ox = p % OSZ;
    int base = bidx * HWSZ * CC;
    int* toff = g_tapoff + ((size_t)k * PP + p) * 16;
    float* tw = g_tapw + ((size_t)k * PP + p) * 16;
#pragma unroll
    for (int s = 0; s < 4; s++) {
        int sy = oy * 2 + (s >> 1);
        int sx = ox * 2 + (s & 1);
        float yv = y1 + bh * ((sy + 0.5f) * 0.5f);
        float xv = x1 + bw * ((sx + 0.5f) * 0.5f);
        bool m = (yv >= -1.f) && (yv <= (float)HH) && (xv >= -1.f) && (xv <= (float)WW);
        float yc = fminf(fmaxf(yv, 0.f), (float)(HH - 1));
        float xc = fminf(fmaxf(xv, 0.f), (float)(WW - 1));
        int yl = (int)floorf(yc);
        int xl = (int)floorf(xc);
        int yh = min(yl + 1, HH - 1);
        int xh = min(xl + 1, WW - 1);
        float ly = yc - (float)yl;
        float lx = xc - (float)xl;
        float sc = m ? 0.25f : 0.f;
        toff[s * 4 + 0] = base + (yl * WW + xl) * CC;
        toff[s * 4 + 1] = base + (yl * WW + xh) * CC;
        toff[s * 4 + 2] = base + (yh * WW + xl) * CC;
        toff[s * 4 + 3] = base + (yh * WW + xh) * CC;
        tw[s * 4 + 0] = sc * (1.f - ly) * (1.f - lx);
        tw[s * 4 + 1] = sc * (1.f - ly) * lx;
        tw[s * 4 + 2] = sc * ly * (1.f - lx);
        tw[s * 4 + 3] = sc * ly * lx;
    }
}

// ---------------- transpose semantic NCHW -> NHWC ----------------
__global__ void k_trans_sem(const float* __restrict__ sem) {
    __shared__ float tile[32][33];
    int b = blockIdx.z;
    int hw0 = blockIdx.x * 32;
    int c0 = blockIdx.y * 32;
    int tx = threadIdx.x, ty = threadIdx.y;
    const float* src = sem + (size_t)b * CC * HWSZ;
    float* dst = g_semT + (size_t)b * HWSZ * CC;
#pragma unroll
    for (int yy = 0; yy < 32; yy += 8)
        tile[ty + yy][tx] = src[(size_t)(c0 + ty + yy) * HWSZ + hw0 + tx];
    __syncthreads();
#pragma unroll
    for (int yy = 0; yy < 32; yy += 8)
        dst[(size_t)(hw0 + ty + yy) * CC + c0 + tx] = tile[tx][ty + yy];
}

// ---------------- ROI align gather: block = (p-chunk of 28, k) ----------------
__global__ __launch_bounds__(256)
void k_roialign() {
    __shared__ int soff[28 * 16];
    __shared__ float sw[28 * 16];
    int k = blockIdx.y;
    int p0 = blockIdx.x * 28;
    int tid = threadIdx.x;
    for (int i = tid; i < 28 * 16; i += 256) {
        soff[i] = g_tapoff[((size_t)k * PP + p0) * 16 + i];
        sw[i] = g_tapw[((size_t)k * PP + p0) * 16 + i];
    }
    __syncthreads();
    int c = tid;
    for (int pp = 0; pp < 28; pp++) {
        float acc = 0.f;
#pragma unroll
        for (int t = 0; t < 16; t++)
            acc += sw[pp * 16 + t] * __ldg(&g_semT[soff[pp * 16 + t] + c]);
        g_roisem[((size_t)k * PP + p0 + pp) * CC + c] = acc;
    }
}

// ---------------- tf32 tensor-core dual 3x3 conv (256 -> 64, fused BN+ReLU) ----------------
__global__ __launch_bounds__(256, 2)
void k_conv_mma(const float* __restrict__ roi_feature,
                const float* __restrict__ bias_sem, const float* __restrict__ bias_fpn) {
    extern __shared__ float dyn[];
    float* act = dyn;
    float* Bsm = dyn + ACT_FLOATS;
    int k = blockIdx.x;
    int tid = threadIdx.x;
    int warp = tid >> 5;
    int lane = tid & 31;
    int g = lane >> 2;
    int t = lane & 3;
    int wrow = warp * 32;

    float acc[2][8][4];
#pragma unroll
    for (int mg = 0; mg < 2; mg++)
#pragma unroll
        for (int n8 = 0; n8 < 8; n8++)
#pragma unroll
            for (int q = 0; q < 4; q++) acc[mg][n8][q] = 0.f;

    const float* rfk = roi_feature + (size_t)k * CC * PP;
    const float* rsk = g_roisem + (size_t)k * PP * CC;

    int brow = tid >> 3;
    int bcol = (tid & 7) * 8;

    for (int ic0 = 0; ic0 < CC; ic0 += ICC) {
        for (int i = tid; i < ACT_FLOATS; i += 256) act[i] = 0.f;
        __syncthreads();
        for (int i = tid; i < PP * ICC; i += 256) {
            int p = i >> 5, icc = i & 31;
            int c = ic0 + icc;
            float v = rsk[(size_t)p * CC + c];
            v = fmaxf(v * g_sc_sem[c] + g_sh_sem[c], 0.f);
            act[icc * ACT_STR + GUARD + (p / OSZ) * 16 + (p % OSZ)] = cvt_tf32(v);
        }
        for (int i = tid; i < ICC * PP; i += 256) {
            int icc = i / PP, p = i % PP;
            int c = ic0 + icc;
            float v = rfk[(size_t)c * PP + p];
            v = fmaxf(v * g_sc_fpn[c] + g_sh_fpn[c], 0.f);
            act[(ICC + icc) * ACT_STR + GUARD + (p / OSZ) * 16 + (p % OSZ)] = cvt_tf32(v);
        }
        {
            const float* w = g_wsemT + (size_t)(ic0 + brow) * 576 + 0 * 64 + bcol;
            float4 a4 = *(const float4*)w;
            float4 b4 = *(const float4*)(w + 4);
            float* d = Bsm + brow * BSTR + bcol;
            d[0] = cvt_tf32(a4.x); d[1] = cvt_tf32(a4.y); d[2] = cvt_tf32(a4.z); d[3] = cvt_tf32(a4.w);
            d[4] = cvt_tf32(b4.x); d[5] = cvt_tf32(b4.y); d[6] = cvt_tf32(b4.z); d[7] = cvt_tf32(b4.w);
        }
        __syncthreads();

        int cur = 0;
        for (int idx = 0; idx < 18; idx++) {
            int br = idx / 9, tap = idx % 9;
            int off = (tap / 3 - 1) * 16 + (tap % 3 - 1);
            float4 pa, pb;
            if (idx < 17) {
                int nbr = (idx + 1) / 9, ntap = (idx + 1) % 9;
                const float* wT = nbr ? g_wfpnT : g_wsemT;
                const float* w = wT + (size_t)(ic0 + brow) * 576 + ntap * 64 + bcol;
                pa = *(const float4*)w;
                pb = *(const float4*)(w + 4);
            }
            const float* actb = act + br * (ICC * ACT_STR);
            const float* Bc = Bsm + cur * (ICC * BSTR);
#pragma unroll
            for (int ks = 0; ks < 4; ks++) {
                unsigned bf[8][2];
#pragma unroll
                for (int n8 = 0; n8 < 8; n8++) {
                    bf[n8][0] = __float_as_uint(Bc[(ks * 8 + t) * BSTR + n8 * 8 + g]);
                    bf[n8][1] = __float_as_uint(Bc[(ks * 8 + t + 4) * BSTR + n8 * 8 + g]);
                }
                unsigned af[2][4];
#pragma unroll
                for (int mg = 0; mg < 2; mg++) {
                    int r0 = GUARD + wrow + mg * 16 + g + off;
                    const float* a0 = actb + (ks * 8 + t) * ACT_STR + r0;
                    const float* a1 = actb + (ks * 8 + t + 4) * ACT_STR + r0;
                    af[mg][0] = __float_as_uint(a0[0]);
                    af[mg][1] = __float_as_uint(a0[8]);
                    af[mg][2] = __float_as_uint(a1[0]);
                    af[mg][3] = __float_as_uint(a1[8]);
                }
#pragma unroll
                for (int mg = 0; mg < 2; mg++)
#pragma unroll
                    for (int n8 = 0; n8 < 8; n8++)
                        mma_tf32(acc[mg][n8], af[mg], bf[n8]);
            }
            __syncthreads();
            if (idx < 17) {
                float* d = Bsm + (cur ^ 1) * (ICC * BSTR) + brow * BSTR + bcol;
                d[0] = cvt_tf32(pa.x); d[1] = cvt_tf32(pa.y); d[2] = cvt_tf32(pa.z); d[3] = cvt_tf32(pa.w);
                d[4] = cvt_tf32(pb.x); d[5] = cvt_tf32(pb.y); d[6] = cvt_tf32(pb.z); d[7] = cvt_tf32(pb.w);
            }
            __syncthreads();
            cur ^= 1;
        }
    }

    float* outsm = act;
#pragma unroll
    for (int mg = 0; mg < 2; mg++) {
        int r0 = wrow + mg * 16 + g;
#pragma unroll
        for (int n8 = 0; n8 < 8; n8++) {
            int oc = n8 * 8 + 2 * t;
            outsm[oc * OUT_STR + r0] = acc[mg][n8][0];
            outsm[(oc + 1) * OUT_STR + r0] = acc[mg][n8][1];
            outsm[oc * OUT_STR + r0 + 8] = acc[mg][n8][2];
            outsm[(oc + 1) * OUT_STR + r0 + 8] = acc[mg][n8][3];
        }
    }
    __syncthreads();
    for (int i = tid; i < 64 * PP; i += 256) {
        int oc = i / PP, p = i % PP;
        float v = outsm[oc * OUT_STR + (p / OSZ) * 16 + (p % OSZ)];
        g_abuf[((size_t)k * 64 + oc) * PP + p] = v + __ldg(&bias_sem[oc]) + __ldg(&bias_fpn[oc]);
    }
}

// ---------------- bn_relu(a) + 1x1 conv(64->196) + sigmoid + degree ----------------
__global__ __launch_bounds__(128)
void k_aff(const float* __restrict__ aff_b) {
    __shared__ float sAr[64][100];
    int k = blockIdx.x;
    int half = blockIdx.y;
    int p0 = half * 98;
    int tid = threadIdx.x;
    for (int i = tid; i < 64 * 98; i += 128) {
        int c = i / 98, pp = i % 98;
        float v = g_abuf[((size_t)k * 64 + c) * PP + p0 + pp];
        sAr[c][pp] = fmaxf(v * g_sc_aff[c] + g_sh_aff[c], 0.f);
    }
    __syncthreads();
    int p = tid;
    if (p < 98) {
        float deg = 0.f;
        for (int ng = 0; ng < 49; ng++) {
            float4 acc;
            acc.x = __ldg(&aff_b[ng * 4 + 0]);
            acc.y = __ldg(&aff_b[ng * 4 + 1]);
            acc.z = __ldg(&aff_b[ng * 4 + 2]);
            acc.w = __ldg(&aff_b[ng * 4 + 3]);
#pragma unroll 8
            for (int c = 0; c < 64; c++) {
                float av = sAr[c][p];
                float4 w4 = __ldg((const float4*)&g_waffT[c * PP + ng * 4]);
                acc.x += av * w4.x;
                acc.y += av * w4.y;
                acc.z += av * w4.z;
                acc.w += av * w4.w;
            }
            float s0 = 1.f / (1.f + expf(-acc.x));
            float s1 = 1.f / (1.f + expf(-acc.y));
            float s2 = 1.f / (1.f + expf(-acc.z));
            float s3 = 1.f / (1.f + expf(-acc.w));
            float* Ao = g_Abuf + ((size_t)k * PP + ng * 4) * PP + p0 + p;
            Ao[0 * PP] = s0;
            Ao[1 * PP] = s1;
            Ao[2 * PP] = s2;
            Ao[3 * PP] = s3;
            deg += s0 + s1 + s2 + s3;
        }
        g_dis[k * PP + p0 + p] = rsqrtf(deg);
    }
}

// ---------------- xw1s ----------------
__global__ __launch_bounds__(224)
void k_xw1(const float* __restrict__ rf, const float* __restrict__ w1) {
    __shared__ __align__(16) float sW1[CC * 16];
    int k = blockIdx.x;
    int tid = threadIdx.x;
    for (int i = tid; i < CC * 16; i += 224) sW1[i] = w1[i];
    __syncthreads();
    int i = tid;
    if (i >= PP) return;
    float acc[16];
#pragma unroll
    for (int f = 0; f < 16; f++) acc[f] = 0.f;
    const float* x = rf + (size_t)k * CC * PP;
    for (int c = 0; c < CC; c++) {
        float v = x[c * PP + i];
#pragma unroll
        for (int fg = 0; fg < 4; fg++) {
            float4 w4 = *(const float4*)&sW1[c * 16 + fg * 4];
            acc[fg * 4 + 0] += v * w4.x;
            acc[fg * 4 + 1] += v * w4.y;
            acc[fg * 4 + 2] += v * w4.z;
            acc[fg * 4 + 3] += v * w4.w;
        }
    }
    float di = g_dis[k * PP + i];
    float* o = g_xw1 + ((size_t)k * PP + i) * 16;
#pragma unroll
    for (int fg = 0; fg < 4; fg++) {
        float4 v;
        v.x = di * acc[fg * 4 + 0];
        v.y = di * acc[fg * 4 + 1];
        v.z = di * acc[fg * 4 + 2];
        v.w = di * acc[fg * 4 + 3];
        *(float4*)&o[fg * 4] = v;
    }
}

// ---------------- agg1 + relu + (x1 @ w2) scaled ----------------
__global__ __launch_bounds__(224)
void k_gcn1(const float* __restrict__ b1, const float* __restrict__ w2) {
    __shared__ __align__(16) float sXW[PP * 16];
    __shared__ __align__(16) float sW2[16 * CC];
    int k = blockIdx.x;
    int tid = threadIdx.x;
    for (int i = tid; i < PP * 16; i += 224) sXW[i] = g_xw1[(size_t)k * PP * 16 + i];
    for (int i = tid; i < 16 * CC; i += 224) sW2[i] = w2[i];
    __syncthreads();
    int j = tid;
    if (j >= PP) return;
    float acc[16];
#pragma unroll
    for (int f = 0; f < 16; f++) acc[f] = 0.f;
    const float* A = g_Abuf + (size_t)k * PP * PP;
    for (int i = 0; i < PP; i++) {
        float a = A[i * PP + j];
#pragma unroll
        for (int fg = 0; fg < 4; fg++) {
            float4 xv = *(const float4*)&sXW[i * 16 + fg * 4];
            acc[fg * 4 + 0] += a * xv.x;
            acc[fg * 4 + 1] += a * xv.y;
            acc[fg * 4 + 2] += a * xv.z;
            acc[fg * 4 + 3] += a * xv.w;
        }
    }
    float dj = g_dis[k * PP + j];
    float x1[16];
#pragma unroll
    for (int f = 0; f < 16; f++) x1[f] = fmaxf(acc[f] * dj + b1[f], 0.f);
    float* o = g_xw2 + ((size_t)k * PP + j) * CC;
    for (int g = 0; g < 64; g++) {
        float4 s = make_float4(0.f, 0.f, 0.f, 0.f);
#pragma unroll
        for (int f = 0; f < 16; f++) {
            float4 w4 = *(const float4*)&sW2[f * CC + g * 4];
            s.x += x1[f] * w4.x;
            s.y += x1[f] * w4.y;
            s.z += x1[f] * w4.z;
            s.w += x1[f] * w4.w;
        }
        s.x *= dj; s.y *= dj; s.z *= dj; s.w *= dj;
        *(float4*)&o[g * 4] = s;
    }
}

// ---------------- agg2 via tf32 mma + bias + add roi_sem -> out ----------------
// C[j][f] = sum_i A[i][j] * X2[i][f]; block = (f-chunk 64, k); 7 warps x 32 rows = 224 >= 196.
__global__ __launch_bounds__(224)
void k_gcn2_mma(const float* __restrict__ b2, float* __restrict__ out) {
    __shared__ float sA[32 * G2_ASTR];
    __shared__ float sX[32 * G2_XSTR];
    int f0 = blockIdx.x * 64;
    int k = blockIdx.y;
    int tid = threadIdx.x;
    int warp = tid >> 5;
    int lane = tid & 31;
    int g = lane >> 2;
    int t = lane & 3;
    int wrow = warp * 32;

    float acc[2][8][4];
#pragma unroll
    for (int mg = 0; mg < 2; mg++)
#pragma unroll
        for (int n8 = 0; n8 < 8; n8++)
#pragma unroll
            for (int q = 0; q < 4; q++) acc[mg][n8][q] = 0.f;

    const float* A = g_Abuf + (size_t)k * PP * PP;
    const float* X2 = g_xw2 + (size_t)k * PP * CC;

    for (int i0 = 0; i0 < 224; i0 += 32) {
        __syncthreads();
        // stage A[i][j]: 32 rows x 224 cols (zero-pad beyond 196)
        for (int ii = 0; ii < 32; ii++) {
            int i = i0 + ii;
            float v = (i < PP && tid < PP) ? A[(size_t)i * PP + tid] : 0.f;
            sA[ii * G2_ASTR + tid] = cvt_tf32(v);
        }
        // stage X2[i][f0+ff]: 32 x 64
        for (int idx = tid; idx < 32 * 64; idx += 224) {
            int ii = idx >> 6, ff = idx & 63;
            int i = i0 + ii;
            float v = (i < PP) ? X2[(size_t)i * CC + f0 + ff] : 0.f;
            sX[ii * G2_XSTR + ff] = cvt_tf32(v);
        }
        __syncthreads();
#pragma unroll
        for (int ks = 0; ks < 4; ks++) {
            unsigned bf[8][2];
#pragma unroll
            for (int n8 = 0; n8 < 8; n8++) {
                bf[n8][0] = __float_as_uint(sX[(ks * 8 + t) * G2_XSTR + n8 * 8 + g]);
                bf[n8][1] = __float_as_uint(sX[(ks * 8 + t + 4) * G2_XSTR + n8 * 8 + g]);
            }
            unsigned af[2][4];
#pragma unroll
            for (int mg = 0; mg < 2; mg++) {
                int r0 = wrow + mg * 16 + g;
                const float* a0 = sA + (ks * 8 + t) * G2_ASTR + r0;
                const float* a1 = sA + (ks * 8 + t + 4) * G2_ASTR + r0;
                af[mg][0] = __float_as_uint(a0[0]);
                af[mg][1] = __float_as_uint(a0[8]);
                af[mg][2] = __float_as_uint(a1[0]);
                af[mg][3] = __float_as_uint(a1[8]);
            }
#pragma unroll
            for (int mg = 0; mg < 2; mg++)
#pragma unroll
                for (int n8 = 0; n8 < 8; n8++)
                    mma_tf32(acc[mg][n8], af[mg], bf[n8]);
        }
    }

    // epilogue: out[k][f][j] = roi_sem[k][j][f] + dis_j * C[j][f] + b2[f]
#pragma unroll
    for (int mg = 0; mg < 2; mg++) {
#pragma unroll
        for (int half = 0; half < 2; half++) {
            int j = wrow + mg * 16 + g + half * 8;
            if (j < PP) {
                float dj = g_dis[k * PP + j];
                const float* rs = g_roisem + ((size_t)k * PP + j) * CC;
#pragma unroll
                for (int n8 = 0; n8 < 8; n8++) {
                    int f = f0 + n8 * 8 + 2 * t;
                    float v0 = acc[mg][n8][half * 2 + 0];
                    float v1 = acc[mg][n8][half * 2 + 1];
                    out[((size_t)k * CC + f) * PP + j] = rs[f] + dj * v0 + __ldg(&b2[f]);
                    out[((size_t)k * CC + f + 1) * PP + j] = rs[f + 1] + dj * v1 + __ldg(&b2[f + 1]);
                }
            }
        }
    }
}

// ---------------- launch ----------------
extern "C" void kernel_launch(void* const* d_in, const int* in_sizes, int n_in,
                              void* d_out, int out_size) {
    const float* roi_feature = (const float*)d_in[0];
    const float* semantic = (const float*)d_in[1];
    const float* boxes = (const float*)d_in[2];
    const float* bn_sem_g = (const float*)d_in[3];
    const float* bn_sem_b = (const float*)d_in[4];
    const float* bn_sem_m = (const float*)d_in[5];
    const float* bn_sem_v = (const float*)d_in[6];
    const float* conv_sem_w = (const float*)d_in[7];
    const float* conv_sem_b = (const float*)d_in[8];
    const float* bn_fpn_g = (const float*)d_in[9];
    const float* bn_fpn_b = (const float*)d_in[10];
    const float* bn_fpn_m = (const float*)d_in[11];
    const float* bn_fpn_v = (const float*)d_in[12];
    const float* conv_fpn_w = (const float*)d_in[13];
    const float* conv_fpn_b = (const float*)d_in[14];
    const float* bn_aff_g = (const float*)d_in[15];
    const float* bn_aff_b = (const float*)d_in[16];
    const float* bn_aff_m = (const float*)d_in[17];
    const float* bn_aff_v = (const float*)d_in[18];
    const float* conv_aff_w = (const float*)d_in[19];
    const float* conv_aff_b = (const float*)d_in[20];
    const float* gcn1_w = (const float*)d_in[21];
    const float* gcn1_b = (const float*)d_in[22];
    const float* gcn2_w = (const float*)d_in[23];
    const float* gcn2_b = (const float*)d_in[24];
    float* out = (float*)d_out;

    static int smem_set = 0;
    if (!smem_set) {
        cudaFuncSetAttribute(k_conv_mma, cudaFuncAttributeMaxDynamicSharedMemorySize, CONV_SMEM);
        smem_set = 1;
    }

    k_prep_scale<<<1, 256>>>(bn_sem_g, bn_sem_b, bn_sem_m, bn_sem_v,
                             bn_fpn_g, bn_fpn_b, bn_fpn_m, bn_fpn_v,
                             bn_aff_g, bn_aff_b, bn_aff_m, bn_aff_v);
    k_prep_wt<<<302, 256>>>(conv_sem_w, conv_fpn_w, conv_aff_w);
    k_roiprep<<<KK, 224>>>(boxes);
    {
        dim3 g(HWSZ / 32, CC / 32, BB);
        dim3 b(32, 8);
        k_trans_sem<<<g, b>>>(semantic);
    }
    {
        dim3 g(7, KK);
        k_roialign<<<g, 256>>>();
    }
    k_conv_mma<<<KK, 256, CONV_SMEM>>>(roi_feature, conv_sem_b, conv_fpn_b);
    {
        dim3 g(KK, 2);
        k_aff<<<g, 128>>>(conv_aff_b);
    }
    k_xw1<<<KK, 224>>>(roi_feature, gcn1_w);
    k_gcn1<<<KK, 224>>>(gcn1_b, gcn2_w);
    {
        dim3 g(4, KK);
        k_gcn2_mma<<<g, 224>>>(gcn2_b, out);
    }
}

// round 6
// speedup vs baseline: 2.6974x; 1.1324x over previous
#include <cuda_runtime.h>
#include <math.h>

#define KK 256
#define CC 256
#define PP 196
#define OSZ 14
#define HH 112
#define WW 112
#define BB 4
#define HWSZ 12544

// conv-mma geometry
#define ICC 32
#define ACT_STR 297
#define GUARD 17
#define BSTR 72
#define ACT_FLOATS (2 * ICC * ACT_STR)
#define B_FLOATS (2 * ICC * BSTR)
#define CONV_SMEM ((ACT_FLOATS + B_FLOATS) * 4)
#define OUT_STR 264

// gcn2-mma geometry
#define G2_ASTR 232
#define G2_XSTR 72

// aff-mma geometry
#define AFF_ASTR 232
#define AFF_WSTR 72
#define AFF_SMEM ((64 * AFF_ASTR + 64 * AFF_WSTR) * 4)

// ---------------- scratch ----------------
__device__ float g_semT[BB * HWSZ * CC];
__device__ float g_roisem[KK * PP * CC];
__device__ float g_abuf[KK * 64 * PP];
__device__ float g_Abuf[KK * PP * PP];
__device__ float g_deg[KK * PP];
__device__ float g_xw1[KK * PP * 16];
__device__ float g_xw2[KK * PP * CC];
__device__ float g_wsemT[CC * 9 * 64];
__device__ float g_wfpnT[CC * 9 * 64];
__device__ float g_waffT[64 * PP];
__device__ int   g_tapoff[KK * PP * 16];
__device__ float g_tapw[KK * PP * 16];
__device__ float g_sc_sem[CC], g_sh_sem[CC];
__device__ float g_sc_fpn[CC], g_sh_fpn[CC];
__device__ float g_sc_aff[64], g_sh_aff[64];

__device__ __forceinline__ float cvt_tf32(float x) {
    unsigned r;
    asm("cvt.rna.tf32.f32 %0, %1;" : "=r"(r) : "f"(x));
    return __uint_as_float(r);
}

__device__ __forceinline__ void mma_tf32(float* c, const unsigned* a, const unsigned* b) {
    asm volatile(
        "mma.sync.aligned.m16n8k8.row.col.f32.tf32.tf32.f32 "
        "{%0,%1,%2,%3}, {%4,%5,%6,%7}, {%8,%9}, {%0,%1,%2,%3};"
        : "+f"(c[0]), "+f"(c[1]), "+f"(c[2]), "+f"(c[3])
        : "r"(a[0]), "r"(a[1]), "r"(a[2]), "r"(a[3]), "r"(b[0]), "r"(b[1]));
}

// ---------------- prep: bn scale/shift ----------------
__global__ void k_prep_scale(const float* gs, const float* bs, const float* ms, const float* vs,
                             const float* gf, const float* bf, const float* mf, const float* vf,
                             const float* ga, const float* ba, const float* ma, const float* va) {
    int t = threadIdx.x;
    if (t < CC) {
        float s = gs[t] * rsqrtf(vs[t] + 1e-5f);
        g_sc_sem[t] = s;
        g_sh_sem[t] = bs[t] - ms[t] * s;
        float f = gf[t] * rsqrtf(vf[t] + 1e-5f);
        g_sc_fpn[t] = f;
        g_sh_fpn[t] = bf[t] - mf[t] * f;
    }
    if (t < 64) {
        float a = ga[t] * rsqrtf(va[t] + 1e-5f);
        g_sc_aff[t] = a;
        g_sh_aff[t] = ba[t] - ma[t] * a;
    }
}

// ---------------- prep: weight transposes ----------------
__global__ void k_prep_wt(const float* wsem, const float* wfpn, const float* waff) {
    const int N1 = CC * 9 * 64;
    const int NA = 64 * PP;
    int total = 2 * N1 + NA;
    for (int d = blockIdx.x * blockDim.x + threadIdx.x; d < total; d += gridDim.x * blockDim.x) {
        if (d < N1) {
            int ic = d / 576, r = d % 576, tap = r / 64, oc = r % 64;
            g_wsemT[d] = wsem[oc * (CC * 9) + ic * 9 + tap];
        } else if (d < 2 * N1) {
            int e = d - N1;
            int ic = e / 576, r = e % 576, tap = r / 64, oc = r % 64;
            g_wfpnT[e] = wfpn[oc * (CC * 9) + ic * 9 + tap];
        } else {
            int e = d - 2 * N1;
            int c = e / PP, n = e % PP;
            g_waffT[e] = waff[n * 64 + c];
        }
    }
}

// ---------------- roi tap prep + deg zero ----------------
__global__ void k_roiprep(const float* __restrict__ boxes) {
    int k = blockIdx.x;
    int p = threadIdx.x;
    if (p >= PP) return;
    g_deg[k * PP + p] = 0.f;
    int bidx = (int)boxes[k * 5 + 0];
    float x1 = boxes[k * 5 + 1], y1 = boxes[k * 5 + 2];
    float x2 = boxes[k * 5 + 3], y2 = boxes[k * 5 + 4];
    float bw = fmaxf(x2 - x1, 1.f) * (1.f / OSZ);
    float bh = fmaxf(y2 - y1, 1.f) * (1.f / OSZ);
    int oy = p / OSZ, ox = p % OSZ;
    int base = bidx * HWSZ * CC;
    int* toff = g_tapoff + ((size_t)k * PP + p) * 16;
    float* tw = g_tapw + ((size_t)k * PP + p) * 16;
#pragma unroll
    for (int s = 0; s < 4; s++) {
        int sy = oy * 2 + (s >> 1);
        int sx = ox * 2 + (s & 1);
        float yv = y1 + bh * ((sy + 0.5f) * 0.5f);
        float xv = x1 + bw * ((sx + 0.5f) * 0.5f);
        bool m = (yv >= -1.f) && (yv <= (float)HH) && (xv >= -1.f) && (xv <= (float)WW);
        float yc = fminf(fmaxf(yv, 0.f), (float)(HH - 1));
        float xc = fminf(fmaxf(xv, 0.f), (float)(WW - 1));
        int yl = (int)floorf(yc);
        int xl = (int)floorf(xc);
        int yh = min(yl + 1, HH - 1);
        int xh = min(xl + 1, WW - 1);
        float ly = yc - (float)yl;
        float lx = xc - (float)xl;
        float sc = m ? 0.25f : 0.f;
        toff[s * 4 + 0] = base + (yl * WW + xl) * CC;
        toff[s * 4 + 1] = base + (yl * WW + xh) * CC;
        toff[s * 4 + 2] = base + (yh * WW + xl) * CC;
        toff[s * 4 + 3] = base + (yh * WW + xh) * CC;
        tw[s * 4 + 0] = sc * (1.f - ly) * (1.f - lx);
        tw[s * 4 + 1] = sc * (1.f - ly) * lx;
        tw[s * 4 + 2] = sc * ly * (1.f - lx);
        tw[s * 4 + 3] = sc * ly * lx;
    }
}

// ---------------- transpose semantic NCHW -> NHWC ----------------
__global__ void k_trans_sem(const float* __restrict__ sem) {
    __shared__ float tile[32][33];
    int b = blockIdx.z;
    int hw0 = blockIdx.x * 32;
    int c0 = blockIdx.y * 32;
    int tx = threadIdx.x, ty = threadIdx.y;
    const float* src = sem + (size_t)b * CC * HWSZ;
    float* dst = g_semT + (size_t)b * HWSZ * CC;
#pragma unroll
    for (int yy = 0; yy < 32; yy += 8)
        tile[ty + yy][tx] = src[(size_t)(c0 + ty + yy) * HWSZ + hw0 + tx];
    __syncthreads();
#pragma unroll
    for (int yy = 0; yy < 32; yy += 8)
        dst[(size_t)(hw0 + ty + yy) * CC + c0 + tx] = tile[tx][ty + yy];
}

// ---------------- ROI align gather ----------------
__global__ __launch_bounds__(256)
void k_roialign() {
    __shared__ int soff[28 * 16];
    __shared__ float sw[28 * 16];
    int k = blockIdx.y;
    int p0 = blockIdx.x * 28;
    int tid = threadIdx.x;
    for (int i = tid; i < 28 * 16; i += 256) {
        soff[i] = g_tapoff[((size_t)k * PP + p0) * 16 + i];
        sw[i] = g_tapw[((size_t)k * PP + p0) * 16 + i];
    }
    __syncthreads();
    int c = tid;
    for (int pp = 0; pp < 28; pp++) {
        float acc = 0.f;
#pragma unroll
        for (int t = 0; t < 16; t++)
            acc += sw[pp * 16 + t] * __ldg(&g_semT[soff[pp * 16 + t] + c]);
        g_roisem[((size_t)k * PP + p0 + pp) * CC + c] = acc;
    }
}

// ---------------- tf32 tensor-core dual 3x3 conv ----------------
__global__ __launch_bounds__(256, 2)
void k_conv_mma(const float* __restrict__ roi_feature,
                const float* __restrict__ bias_sem, const float* __restrict__ bias_fpn) {
    extern __shared__ float dyn[];
    float* act = dyn;
    float* Bsm = dyn + ACT_FLOATS;
    int k = blockIdx.x;
    int tid = threadIdx.x;
    int warp = tid >> 5;
    int lane = tid & 31;
    int g = lane >> 2;
    int t = lane & 3;
    int wrow = warp * 32;

    float acc[2][8][4];
#pragma unroll
    for (int mg = 0; mg < 2; mg++)
#pragma unroll
        for (int n8 = 0; n8 < 8; n8++)
#pragma unroll
            for (int q = 0; q < 4; q++) acc[mg][n8][q] = 0.f;

    const float* rfk = roi_feature + (size_t)k * CC * PP;
    const float* rsk = g_roisem + (size_t)k * PP * CC;

    int brow = tid >> 3;
    int bcol = (tid & 7) * 8;

    // zero act tiles ONCE (guards never rewritten; interior fully rewritten per chunk)
    for (int i = tid; i < ACT_FLOATS; i += 256) act[i] = 0.f;
    __syncthreads();

    for (int ic0 = 0; ic0 < CC; ic0 += ICC) {
        for (int i = tid; i < PP * ICC; i += 256) {
            int p = i >> 5, icc = i & 31;
            int c = ic0 + icc;
            float v = rsk[(size_t)p * CC + c];
            v = fmaxf(v * g_sc_sem[c] + g_sh_sem[c], 0.f);
            act[icc * ACT_STR + GUARD + (p / OSZ) * 16 + (p % OSZ)] = cvt_tf32(v);
        }
        for (int i = tid; i < ICC * PP; i += 256) {
            int icc = i / PP, p = i % PP;
            int c = ic0 + icc;
            float v = rfk[(size_t)c * PP + p];
            v = fmaxf(v * g_sc_fpn[c] + g_sh_fpn[c], 0.f);
            act[(ICC + icc) * ACT_STR + GUARD + (p / OSZ) * 16 + (p % OSZ)] = cvt_tf32(v);
        }
        {
            const float* w = g_wsemT + (size_t)(ic0 + brow) * 576 + 0 * 64 + bcol;
            float4 a4 = *(const float4*)w;
            float4 b4 = *(const float4*)(w + 4);
            float* d = Bsm + brow * BSTR + bcol;
            d[0] = cvt_tf32(a4.x); d[1] = cvt_tf32(a4.y); d[2] = cvt_tf32(a4.z); d[3] = cvt_tf32(a4.w);
            d[4] = cvt_tf32(b4.x); d[5] = cvt_tf32(b4.y); d[6] = cvt_tf32(b4.z); d[7] = cvt_tf32(b4.w);
        }
        __syncthreads();

        int cur = 0;
        for (int idx = 0; idx < 18; idx++) {
            int br = idx / 9, tap = idx % 9;
            int off = (tap / 3 - 1) * 16 + (tap % 3 - 1);
            float4 pa, pb;
            if (idx < 17) {
                int nbr = (idx + 1) / 9, ntap = (idx + 1) % 9;
                const float* wT = nbr ? g_wfpnT : g_wsemT;
                const float* w = wT + (size_t)(ic0 + brow) * 576 + ntap * 64 + bcol;
                pa = *(const float4*)w;
                pb = *(const float4*)(w + 4);
            }
            const float* actb = act + br * (ICC * ACT_STR);
            const float* Bc = Bsm + cur * (ICC * BSTR);
#pragma unroll
            for (int ks = 0; ks < 4; ks++) {
                unsigned bf[8][2];
#pragma unroll
                for (int n8 = 0; n8 < 8; n8++) {
                    bf[n8][0] = __float_as_uint(Bc[(ks * 8 + t) * BSTR + n8 * 8 + g]);
                    bf[n8][1] = __float_as_uint(Bc[(ks * 8 + t + 4) * BSTR + n8 * 8 + g]);
                }
                unsigned af[2][4];
#pragma unroll
                for (int mg = 0; mg < 2; mg++) {
                    int r0 = GUARD + wrow + mg * 16 + g + off;
                    const float* a0 = actb + (ks * 8 + t) * ACT_STR + r0;
                    const float* a1 = actb + (ks * 8 + t + 4) * ACT_STR + r0;
                    af[mg][0] = __float_as_uint(a0[0]);
                    af[mg][1] = __float_as_uint(a0[8]);
                    af[mg][2] = __float_as_uint(a1[0]);
                    af[mg][3] = __float_as_uint(a1[8]);
                }
#pragma unroll
                for (int mg = 0; mg < 2; mg++)
#pragma unroll
                    for (int n8 = 0; n8 < 8; n8++)
                        mma_tf32(acc[mg][n8], af[mg], bf[n8]);
            }
            __syncthreads();
            if (idx < 17) {
                float* d = Bsm + (cur ^ 1) * (ICC * BSTR) + brow * BSTR + bcol;
                d[0] = cvt_tf32(pa.x); d[1] = cvt_tf32(pa.y); d[2] = cvt_tf32(pa.z); d[3] = cvt_tf32(pa.w);
                d[4] = cvt_tf32(pb.x); d[5] = cvt_tf32(pb.y); d[6] = cvt_tf32(pb.z); d[7] = cvt_tf32(pb.w);
            }
            __syncthreads();
            cur ^= 1;
        }
    }

    float* outsm = act;
#pragma unroll
    for (int mg = 0; mg < 2; mg++) {
        int r0 = wrow + mg * 16 + g;
#pragma unroll
        for (int n8 = 0; n8 < 8; n8++) {
            int oc = n8 * 8 + 2 * t;
            outsm[oc * OUT_STR + r0] = acc[mg][n8][0];
            outsm[(oc + 1) * OUT_STR + r0] = acc[mg][n8][1];
            outsm[oc * OUT_STR + r0 + 8] = acc[mg][n8][2];
            outsm[(oc + 1) * OUT_STR + r0 + 8] = acc[mg][n8][3];
        }
    }
    __syncthreads();
    for (int i = tid; i < 64 * PP; i += 256) {
        int oc = i / PP, p = i % PP;
        float v = outsm[oc * OUT_STR + (p / OSZ) * 16 + (p % OSZ)];
        g_abuf[((size_t)k * 64 + oc) * PP + p] = v + __ldg(&bias_sem[oc]) + __ldg(&bias_fpn[oc]);
    }
}

// ---------------- aff via tf32 mma: bn_relu(a) @ w_aff + sigmoid + deg partials ----------------
// C[p][n] = sum_c Ar[p][c] * W[c][n]; block = (n-chunk of 56, k); A[k][n][p] = sigmoid(C + b[n]).
__global__ __launch_bounds__(224)
void k_aff_mma(const float* __restrict__ aff_b) {
    extern __shared__ float dyn[];
    float* sA = dyn;                      // [c][p] 64 x AFF_ASTR
    float* sW = dyn + 64 * AFF_ASTR;      // [c][nn] 64 x AFF_WSTR
    int n0 = blockIdx.x * 56;
    int k = blockIdx.y;
    int tid = threadIdx.x;
    int warp = tid >> 5;
    int lane = tid & 31;
    int g = lane >> 2;
    int t = lane & 3;
    int wrow = warp * 32;

    // stage Ar (bn_relu of abuf), c-major: coalesced over p
    for (int idx = tid; idx < 64 * 224; idx += 224) {
        int c = idx / 224, p = idx % 224;
        float v = 0.f;
        if (p < PP) {
            float a = g_abuf[((size_t)k * 64 + c) * PP + p];
            v = fmaxf(a * g_sc_aff[c] + g_sh_aff[c], 0.f);
        }
        sA[c * AFF_ASTR + p] = cvt_tf32(v);
    }
    // stage W chunk
    for (int idx = tid; idx < 64 * 56; idx += 224) {
        int c = idx / 56, nn = idx % 56;
        int n = n0 + nn;
        float v = (n < PP) ? g_waffT[c * PP + n] : 0.f;
        sW[c * AFF_WSTR + nn] = cvt_tf32(v);
    }
    __syncthreads();

    float acc[2][7][4];
#pragma unroll
    for (int mg = 0; mg < 2; mg++)
#pragma unroll
        for (int n8 = 0; n8 < 7; n8++)
#pragma unroll
            for (int q = 0; q < 4; q++) acc[mg][n8][q] = 0.f;

#pragma unroll
    for (int ks = 0; ks < 8; ks++) {
        unsigned bf[7][2];
#pragma unroll
        for (int n8 = 0; n8 < 7; n8++) {
            bf[n8][0] = __float_as_uint(sW[(ks * 8 + t) * AFF_WSTR + n8 * 8 + g]);
            bf[n8][1] = __float_as_uint(sW[(ks * 8 + t + 4) * AFF_WSTR + n8 * 8 + g]);
        }
        unsigned af[2][4];
#pragma unroll
        for (int mg = 0; mg < 2; mg++) {
            int r0 = wrow + mg * 16 + g;
            const float* a0 = sA + (ks * 8 + t) * AFF_ASTR + r0;
            const float* a1 = sA + (ks * 8 + t + 4) * AFF_ASTR + r0;
            af[mg][0] = __float_as_uint(a0[0]);
            af[mg][1] = __float_as_uint(a0[8]);
            af[mg][2] = __float_as_uint(a1[0]);
            af[mg][3] = __float_as_uint(a1[8]);
        }
#pragma unroll
        for (int mg = 0; mg < 2; mg++)
#pragma unroll
            for (int n8 = 0; n8 < 7; n8++)
                mma_tf32(acc[mg][n8], af[mg], bf[n8]);
    }

    // epilogue: sigmoid + store A[k][n][p] + deg partial per p
    float* Ak = g_Abuf + (size_t)k * PP * PP;
#pragma unroll
    for (int mg = 0; mg < 2; mg++) {
#pragma unroll
        for (int half = 0; half < 2; half++) {
            int p = wrow + mg * 16 + g + half * 8;
            if (p < PP) {
                float dpart = 0.f;
#pragma unroll
                for (int n8 = 0; n8 < 7; n8++) {
#pragma unroll
                    for (int q = 0; q < 2; q++) {
                        int n = n0 + n8 * 8 + 2 * t + q;
                        if (n < PP) {
                            float v = acc[mg][n8][half * 2 + q] + __ldg(&aff_b[n]);
                            float s = 1.f / (1.f + expf(-v));
                            Ak[(size_t)n * PP + p] = s;
                            dpart += s;
                        }
                    }
                }
                atomicAdd(&g_deg[k * PP + p], dpart);
            }
        }
    }
}

// ---------------- xw1s ----------------
__global__ __launch_bounds__(224)
void k_xw1(const float* __restrict__ rf, const float* __restrict__ w1) {
    __shared__ __align__(16) float sW1[CC * 16];
    int k = blockIdx.x;
    int tid = threadIdx.x;
    for (int i = tid; i < CC * 16; i += 224) sW1[i] = w1[i];
    __syncthreads();
    int i = tid;
    if (i >= PP) return;
    float acc[16];
#pragma unroll
    for (int f = 0; f < 16; f++) acc[f] = 0.f;
    const float* x = rf + (size_t)k * CC * PP;
    for (int c = 0; c < CC; c++) {
        float v = x[c * PP + i];
#pragma unroll
        for (int fg = 0; fg < 4; fg++) {
            float4 w4 = *(const float4*)&sW1[c * 16 + fg * 4];
            acc[fg * 4 + 0] += v * w4.x;
            acc[fg * 4 + 1] += v * w4.y;
            acc[fg * 4 + 2] += v * w4.z;
            acc[fg * 4 + 3] += v * w4.w;
        }
    }
    float di = rsqrtf(g_deg[k * PP + i]);
    float* o = g_xw1 + ((size_t)k * PP + i) * 16;
#pragma unroll
    for (int fg = 0; fg < 4; fg++) {
        float4 v;
        v.x = di * acc[fg * 4 + 0];
        v.y = di * acc[fg * 4 + 1];
        v.z = di * acc[fg * 4 + 2];
        v.w = di * acc[fg * 4 + 3];
        *(float4*)&o[fg * 4] = v;
    }
}

// ---------------- agg1 + relu + (x1 @ w2) scaled ----------------
__global__ __launch_bounds__(224)
void k_gcn1(const float* __restrict__ b1, const float* __restrict__ w2) {
    __shared__ __align__(16) float sXW[PP * 16];
    __shared__ __align__(16) float sW2[16 * CC];
    int k = blockIdx.x;
    int tid = threadIdx.x;
    for (int i = tid; i < PP * 16; i += 224) sXW[i] = g_xw1[(size_t)k * PP * 16 + i];
    for (int i = tid; i < 16 * CC; i += 224) sW2[i] = w2[i];
    __syncthreads();
    int j = tid;
    if (j >= PP) return;
    float acc[16];
#pragma unroll
    for (int f = 0; f < 16; f++) acc[f] = 0.f;
    const float* A = g_Abuf + (size_t)k * PP * PP;
    for (int i = 0; i < PP; i++) {
        float a = A[i * PP + j];
#pragma unroll
        for (int fg = 0; fg < 4; fg++) {
            float4 xv = *(const float4*)&sXW[i * 16 + fg * 4];
            acc[fg * 4 + 0] += a * xv.x;
            acc[fg * 4 + 1] += a * xv.y;
            acc[fg * 4 + 2] += a * xv.z;
            acc[fg * 4 + 3] += a * xv.w;
        }
    }
    float dj = rsqrtf(g_deg[k * PP + j]);
    float x1[16];
#pragma unroll
    for (int f = 0; f < 16; f++) x1[f] = fmaxf(acc[f] * dj + b1[f], 0.f);
    float* o = g_xw2 + ((size_t)k * PP + j) * CC;
    for (int g = 0; g < 64; g++) {
        float4 s = make_float4(0.f, 0.f, 0.f, 0.f);
#pragma unroll
        for (int f = 0; f < 16; f++) {
            float4 w4 = *(const float4*)&sW2[f * CC + g * 4];
            s.x += x1[f] * w4.x;
            s.y += x1[f] * w4.y;
            s.z += x1[f] * w4.z;
            s.w += x1[f] * w4.w;
        }
        s.x *= dj; s.y *= dj; s.z *= dj; s.w *= dj;
        *(float4*)&o[g * 4] = s;
    }
}

// ---------------- agg2 via tf32 mma + bias + add roi_sem -> out ----------------
__global__ __launch_bounds__(224)
void k_gcn2_mma(const float* __restrict__ b2, float* __restrict__ out) {
    __shared__ float sA[32 * G2_ASTR];
    __shared__ float sX[32 * G2_XSTR];
    int f0 = blockIdx.x * 64;
    int k = blockIdx.y;
    int tid = threadIdx.x;
    int warp = tid >> 5;
    int lane = tid & 31;
    int g = lane >> 2;
    int t = lane & 3;
    int wrow = warp * 32;

    float acc[2][8][4];
#pragma unroll
    for (int mg = 0; mg < 2; mg++)
#pragma unroll
        for (int n8 = 0; n8 < 8; n8++)
#pragma unroll
            for (int q = 0; q < 4; q++) acc[mg][n8][q] = 0.f;

    const float* A = g_Abuf + (size_t)k * PP * PP;
    const float* X2 = g_xw2 + (size_t)k * PP * CC;

    for (int i0 = 0; i0 < 224; i0 += 32) {
        __syncthreads();
        for (int ii = 0; ii < 32; ii++) {
            int i = i0 + ii;
            float v = (i < PP && tid < PP) ? A[(size_t)i * PP + tid] : 0.f;
            sA[ii * G2_ASTR + tid] = cvt_tf32(v);
        }
        for (int idx = tid; idx < 32 * 64; idx += 224) {
            int ii = idx >> 6, ff = idx & 63;
            int i = i0 + ii;
            float v = (i < PP) ? X2[(size_t)i * CC + f0 + ff] : 0.f;
            sX[ii * G2_XSTR + ff] = cvt_tf32(v);
        }
        __syncthreads();
#pragma unroll
        for (int ks = 0; ks < 4; ks++) {
            unsigned bf[8][2];
#pragma unroll
            for (int n8 = 0; n8 < 8; n8++) {
                bf[n8][0] = __float_as_uint(sX[(ks * 8 + t) * G2_XSTR + n8 * 8 + g]);
                bf[n8][1] = __float_as_uint(sX[(ks * 8 + t + 4) * G2_XSTR + n8 * 8 + g]);
            }
            unsigned af[2][4];
#pragma unroll
            for (int mg = 0; mg < 2; mg++) {
                int r0 = wrow + mg * 16 + g;
                const float* a0 = sA + (ks * 8 + t) * G2_ASTR + r0;
                const float* a1 = sA + (ks * 8 + t + 4) * G2_ASTR + r0;
                af[mg][0] = __float_as_uint(a0[0]);
                af[mg][1] = __float_as_uint(a0[8]);
                af[mg][2] = __float_as_uint(a1[0]);
                af[mg][3] = __float_as_uint(a1[8]);
            }
#pragma unroll
            for (int mg = 0; mg < 2; mg++)
#pragma unroll
                for (int n8 = 0; n8 < 8; n8++)
                    mma_tf32(acc[mg][n8], af[mg], bf[n8]);
        }
    }

#pragma unroll
    for (int mg = 0; mg < 2; mg++) {
#pragma unroll
        for (int half = 0; half < 2; half++) {
            int j = wrow + mg * 16 + g + half * 8;
            if (j < PP) {
                float dj = rsqrtf(g_deg[k * PP + j]);
                const float* rs = g_roisem + ((size_t)k * PP + j) * CC;
#pragma unroll
                for (int n8 = 0; n8 < 8; n8++) {
                    int f = f0 + n8 * 8 + 2 * t;
                    float v0 = acc[mg][n8][half * 2 + 0];
                    float v1 = acc[mg][n8][half * 2 + 1];
                    out[((size_t)k * CC + f) * PP + j] = rs[f] + dj * v0 + __ldg(&b2[f]);
                    out[((size_t)k * CC + f + 1) * PP + j] = rs[f + 1] + dj * v1 + __ldg(&b2[f + 1]);
                }
            }
        }
    }
}

// ---------------- launch ----------------
extern "C" void kernel_launch(void* const* d_in, const int* in_sizes, int n_in,
                              void* d_out, int out_size) {
    const float* roi_feature = (const float*)d_in[0];
    const float* semantic = (const float*)d_in[1];
    const float* boxes = (const float*)d_in[2];
    const float* bn_sem_g = (const float*)d_in[3];
    const float* bn_sem_b = (const float*)d_in[4];
    const float* bn_sem_m = (const float*)d_in[5];
    const float* bn_sem_v = (const float*)d_in[6];
    const float* conv_sem_w = (const float*)d_in[7];
    const float* conv_sem_b = (const float*)d_in[8];
    const float* bn_fpn_g = (const float*)d_in[9];
    const float* bn_fpn_b = (const float*)d_in[10];
    const float* bn_fpn_m = (const float*)d_in[11];
    const float* bn_fpn_v = (const float*)d_in[12];
    const float* conv_fpn_w = (const float*)d_in[13];
    const float* conv_fpn_b = (const float*)d_in[14];
    const float* bn_aff_g = (const float*)d_in[15];
    const float* bn_aff_b = (const float*)d_in[16];
    const float* bn_aff_m = (const float*)d_in[17];
    const float* bn_aff_v = (const float*)d_in[18];
    const float* conv_aff_w = (const float*)d_in[19];
    const float* conv_aff_b = (const float*)d_in[20];
    const float* gcn1_w = (const float*)d_in[21];
    const float* gcn1_b = (const float*)d_in[22];
    const float* gcn2_w = (const float*)d_in[23];
    const float* gcn2_b = (const float*)d_in[24];
    float* out = (float*)d_out;

    static int smem_set = 0;
    if (!smem_set) {
        cudaFuncSetAttribute(k_conv_mma, cudaFuncAttributeMaxDynamicSharedMemorySize, CONV_SMEM);
        cudaFuncSetAttribute(k_aff_mma, cudaFuncAttributeMaxDynamicSharedMemorySize, AFF_SMEM);
        smem_set = 1;
    }

    k_prep_scale<<<1, 256>>>(bn_sem_g, bn_sem_b, bn_sem_m, bn_sem_v,
                             bn_fpn_g, bn_fpn_b, bn_fpn_m, bn_fpn_v,
                             bn_aff_g, bn_aff_b, bn_aff_m, bn_aff_v);
    k_prep_wt<<<302, 256>>>(conv_sem_w, conv_fpn_w, conv_aff_w);
    k_roiprep<<<KK, 224>>>(boxes);
    {
        dim3 g(HWSZ / 32, CC / 32, BB);
        dim3 b(32, 8);
        k_trans_sem<<<g, b>>>(semantic);
    }
    {
        dim3 g(7, KK);
        k_roialign<<<g, 256>>>();
    }
    k_conv_mma<<<KK, 256, CONV_SMEM>>>(roi_feature, conv_sem_b, conv_fpn_b);
    {
        dim3 g(4, KK);
        k_aff_mma<<<g, 224, AFF_SMEM>>>(conv_aff_b);
    }
    k_xw1<<<KK, 224>>>(roi_feature, gcn1_w);
    k_gcn1<<<KK, 224>>>(gcn1_b, gcn2_w);
    {
        dim3 g(4, KK);
        k_gcn2_mma<<<g, 224>>>(gcn2_b, out);
    }
}

// round 7
// speedup vs baseline: 2.7395x; 1.0156x over previous
#include <cuda_runtime.h>
#include <math.h>

#define KK 256
#define CC 256
#define PP 196
#define OSZ 14
#define HH 112
#define WW 112
#define BB 4
#define HWSZ 12544

// conv-mma geometry
#define ICC 32
#define ACT_STR 297
#define GUARD 17
#define BSTR 72
#define ACT_FLOATS (2 * ICC * ACT_STR)
#define B_FLOATS (2 * ICC * BSTR)
#define CONV_SMEM ((ACT_FLOATS + B_FLOATS) * 4)
#define OUT_STR 264

// gcn2-mma geometry
#define G2_ASTR 232
#define G2_XSTR 72

// aff-mma geometry
#define AFF_ASTR 232
#define AFF_WSTR 72
#define AFF_SMEM ((64 * AFF_ASTR + 64 * AFF_WSTR) * 4)

// ---------------- scratch ----------------
__device__ float g_semT[BB * HWSZ * CC];
__device__ float g_roisem[KK * PP * CC];
__device__ float g_abuf[KK * 64 * PP];
__device__ float g_Abuf[KK * PP * PP];
__device__ float g_deg[KK * PP];
__device__ float g_xw1[KK * PP * 16];
__device__ float g_xw2[KK * PP * CC];
__device__ float g_wsemT[CC * 9 * 64];
__device__ float g_wfpnT[CC * 9 * 64];
__device__ float g_waffT[64 * PP];
__device__ int   g_tapoff[KK * PP * 16];
__device__ float g_tapw[KK * PP * 16];
__device__ float g_sc_sem[CC], g_sh_sem[CC];
__device__ float g_sc_fpn[CC], g_sh_fpn[CC];
__device__ float g_sc_aff[64], g_sh_aff[64];

__device__ __forceinline__ float cvt_tf32(float x) {
    unsigned r;
    asm("cvt.rna.tf32.f32 %0, %1;" : "=r"(r) : "f"(x));
    return __uint_as_float(r);
}

__device__ __forceinline__ void mma_tf32(float* c, const unsigned* a, const unsigned* b) {
    asm volatile(
        "mma.sync.aligned.m16n8k8.row.col.f32.tf32.tf32.f32 "
        "{%0,%1,%2,%3}, {%4,%5,%6,%7}, {%8,%9}, {%0,%1,%2,%3};"
        : "+f"(c[0]), "+f"(c[1]), "+f"(c[2]), "+f"(c[3])
        : "r"(a[0]), "r"(a[1]), "r"(a[2]), "r"(a[3]), "r"(b[0]), "r"(b[1]));
}

// ---------------- merged prep: roi taps + bn scales + weight transposes ----------------
// blocks [0, KK): roiprep for k = blockIdx; block KK: bn scales; blocks (KK, KK+128]: wt transpose.
__global__ void k_prep_all(const float* __restrict__ boxes,
                           const float* gs, const float* bs, const float* ms, const float* vs,
                           const float* gf, const float* bfn, const float* mf, const float* vf,
                           const float* ga, const float* ba, const float* ma, const float* va,
                           const float* wsem, const float* wfpn, const float* waff) {
    int bid = blockIdx.x;
    int tid = threadIdx.x;
    if (bid < KK) {
        int k = bid;
        int p = tid;
        if (p >= PP) return;
        g_deg[k * PP + p] = 0.f;
        int bidx = (int)boxes[k * 5 + 0];
        float x1 = boxes[k * 5 + 1], y1 = boxes[k * 5 + 2];
        float x2 = boxes[k * 5 + 3], y2 = boxes[k * 5 + 4];
        float bw = fmaxf(x2 - x1, 1.f) * (1.f / OSZ);
        float bh = fmaxf(y2 - y1, 1.f) * (1.f / OSZ);
        int oy = p / OSZ, ox = p % OSZ;
        int base = bidx * HWSZ * CC;
        int* toff = g_tapoff + ((size_t)k * PP + p) * 16;
        float* tw = g_tapw + ((size_t)k * PP + p) * 16;
#pragma unroll
        for (int s = 0; s < 4; s++) {
            int sy = oy * 2 + (s >> 1);
            int sx = ox * 2 + (s & 1);
            float yv = y1 + bh * ((sy + 0.5f) * 0.5f);
            float xv = x1 + bw * ((sx + 0.5f) * 0.5f);
            bool m = (yv >= -1.f) && (yv <= (float)HH) && (xv >= -1.f) && (xv <= (float)WW);
            float yc = fminf(fmaxf(yv, 0.f), (float)(HH - 1));
            float xc = fminf(fmaxf(xv, 0.f), (float)(WW - 1));
            int yl = (int)floorf(yc);
            int xl = (int)floorf(xc);
            int yh = min(yl + 1, HH - 1);
            int xh = min(xl + 1, WW - 1);
            float ly = yc - (float)yl;
            float lx = xc - (float)xl;
            float sc = m ? 0.25f : 0.f;
            toff[s * 4 + 0] = base + (yl * WW + xl) * CC;
            toff[s * 4 + 1] = base + (yl * WW + xh) * CC;
            toff[s * 4 + 2] = base + (yh * WW + xl) * CC;
            toff[s * 4 + 3] = base + (yh * WW + xh) * CC;
            tw[s * 4 + 0] = sc * (1.f - ly) * (1.f - lx);
            tw[s * 4 + 1] = sc * (1.f - ly) * lx;
            tw[s * 4 + 2] = sc * ly * (1.f - lx);
            tw[s * 4 + 3] = sc * ly * lx;
        }
    } else if (bid == KK) {
        int t = tid;
        if (t < CC) {
            float s = gs[t] * rsqrtf(vs[t] + 1e-5f);
            g_sc_sem[t] = s;
            g_sh_sem[t] = bs[t] - ms[t] * s;
            float f = gf[t] * rsqrtf(vf[t] + 1e-5f);
            g_sc_fpn[t] = f;
            g_sh_fpn[t] = bfn[t] - mf[t] * f;
        }
        if (t < 64) {
            float a = ga[t] * rsqrtf(va[t] + 1e-5f);
            g_sc_aff[t] = a;
            g_sh_aff[t] = ba[t] - ma[t] * a;
        }
    } else {
        const int N1 = CC * 9 * 64;
        const int NA = 64 * PP;
        int total = 2 * N1 + NA;
        int stride = 128 * 256;
        for (int d = (bid - KK - 1) * 256 + tid; d < total; d += stride) {
            if (d < N1) {
                int ic = d / 576, r = d % 576, tap = r / 64, oc = r % 64;
                g_wsemT[d] = wsem[oc * (CC * 9) + ic * 9 + tap];
            } else if (d < 2 * N1) {
                int e = d - N1;
                int ic = e / 576, r = e % 576, tap = r / 64, oc = r % 64;
                g_wfpnT[e] = wfpn[oc * (CC * 9) + ic * 9 + tap];
            } else {
                int e = d - 2 * N1;
                int c = e / PP, n = e % PP;
                g_waffT[e] = waff[n * 64 + c];
            }
        }
    }
}

// ---------------- transpose semantic NCHW -> NHWC ----------------
__global__ void k_trans_sem(const float* __restrict__ sem) {
    __shared__ float tile[32][33];
    int b = blockIdx.z;
    int hw0 = blockIdx.x * 32;
    int c0 = blockIdx.y * 32;
    int tx = threadIdx.x, ty = threadIdx.y;
    const float* src = sem + (size_t)b * CC * HWSZ;
    float* dst = g_semT + (size_t)b * HWSZ * CC;
#pragma unroll
    for (int yy = 0; yy < 32; yy += 8)
        tile[ty + yy][tx] = src[(size_t)(c0 + ty + yy) * HWSZ + hw0 + tx];
    __syncthreads();
#pragma unroll
    for (int yy = 0; yy < 32; yy += 8)
        dst[(size_t)(hw0 + ty + yy) * CC + c0 + tx] = tile[tx][ty + yy];
}

// ---------------- ROI align gather ----------------
__global__ __launch_bounds__(256)
void k_roialign() {
    __shared__ int soff[28 * 16];
    __shared__ float sw[28 * 16];
    int k = blockIdx.y;
    int p0 = blockIdx.x * 28;
    int tid = threadIdx.x;
    for (int i = tid; i < 28 * 16; i += 256) {
        soff[i] = g_tapoff[((size_t)k * PP + p0) * 16 + i];
        sw[i] = g_tapw[((size_t)k * PP + p0) * 16 + i];
    }
    __syncthreads();
    int c = tid;
    for (int pp = 0; pp < 28; pp++) {
        float acc = 0.f;
#pragma unroll
        for (int t = 0; t < 16; t++)
            acc += sw[pp * 16 + t] * __ldg(&g_semT[soff[pp * 16 + t] + c]);
        g_roisem[((size_t)k * PP + p0 + pp) * CC + c] = acc;
    }
}

// ---------------- tf32 tensor-core dual 3x3 conv ----------------
// warps 0-6 compute M rows [0,224) (ppad max 221); warp 7 stages only.
__global__ __launch_bounds__(256, 2)
void k_conv_mma(const float* __restrict__ roi_feature,
                const float* __restrict__ bias_sem, const float* __restrict__ bias_fpn) {
    extern __shared__ float dyn[];
    float* act = dyn;
    float* Bsm = dyn + ACT_FLOATS;
    int k = blockIdx.x;
    int tid = threadIdx.x;
    int warp = tid >> 5;
    int lane = tid & 31;
    int g = lane >> 2;
    int t = lane & 3;
    int wrow = warp * 32;

    float acc[2][8][4];
#pragma unroll
    for (int mg = 0; mg < 2; mg++)
#pragma unroll
        for (int n8 = 0; n8 < 8; n8++)
#pragma unroll
            for (int q = 0; q < 4; q++) acc[mg][n8][q] = 0.f;

    const float* rfk = roi_feature + (size_t)k * CC * PP;
    const float* rsk = g_roisem + (size_t)k * PP * CC;

    int brow = tid >> 3;
    int bcol = (tid & 7) * 8;

    // zero act tiles once (guards never rewritten; interior fully rewritten per chunk)
    for (int i = tid; i < ACT_FLOATS; i += 256) act[i] = 0.f;
    __syncthreads();

    for (int ic0 = 0; ic0 < CC; ic0 += ICC) {
        for (int i = tid; i < PP * ICC; i += 256) {
            int p = i >> 5, icc = i & 31;
            int c = ic0 + icc;
            float v = rsk[(size_t)p * CC + c];
            v = fmaxf(v * g_sc_sem[c] + g_sh_sem[c], 0.f);
            act[icc * ACT_STR + GUARD + (p / OSZ) * 16 + (p % OSZ)] = cvt_tf32(v);
        }
        for (int i = tid; i < ICC * PP; i += 256) {
            int icc = i / PP, p = i % PP;
            int c = ic0 + icc;
            float v = rfk[(size_t)c * PP + p];
            v = fmaxf(v * g_sc_fpn[c] + g_sh_fpn[c], 0.f);
            act[(ICC + icc) * ACT_STR + GUARD + (p / OSZ) * 16 + (p % OSZ)] = cvt_tf32(v);
        }
        {
            const float* w = g_wsemT + (size_t)(ic0 + brow) * 576 + 0 * 64 + bcol;
            float4 a4 = *(const float4*)w;
            float4 b4 = *(const float4*)(w + 4);
            float* d = Bsm + brow * BSTR + bcol;
            d[0] = cvt_tf32(a4.x); d[1] = cvt_tf32(a4.y); d[2] = cvt_tf32(a4.z); d[3] = cvt_tf32(a4.w);
            d[4] = cvt_tf32(b4.x); d[5] = cvt_tf32(b4.y); d[6] = cvt_tf32(b4.z); d[7] = cvt_tf32(b4.w);
        }
        __syncthreads();

        int cur = 0;
        for (int idx = 0; idx < 18; idx++) {
            int br = idx / 9, tap = idx % 9;
            int off = (tap / 3 - 1) * 16 + (tap % 3 - 1);
            float4 pa, pb;
            if (idx < 17) {
                int nbr = (idx + 1) / 9, ntap = (idx + 1) % 9;
                const float* wT = nbr ? g_wfpnT : g_wsemT;
                const float* w = wT + (size_t)(ic0 + brow) * 576 + ntap * 64 + bcol;
                pa = *(const float4*)w;
                pb = *(const float4*)(w + 4);
            }
            if (warp < 7) {
                const float* actb = act + br * (ICC * ACT_STR);
                const float* Bc = Bsm + cur * (ICC * BSTR);
#pragma unroll
                for (int ks = 0; ks < 4; ks++) {
                    unsigned bf[8][2];
#pragma unroll
                    for (int n8 = 0; n8 < 8; n8++) {
                        bf[n8][0] = __float_as_uint(Bc[(ks * 8 + t) * BSTR + n8 * 8 + g]);
                        bf[n8][1] = __float_as_uint(Bc[(ks * 8 + t + 4) * BSTR + n8 * 8 + g]);
                    }
                    unsigned af[2][4];
#pragma unroll
                    for (int mg = 0; mg < 2; mg++) {
                        int r0 = GUARD + wrow + mg * 16 + g + off;
                        const float* a0 = actb + (ks * 8 + t) * ACT_STR + r0;
                        const float* a1 = actb + (ks * 8 + t + 4) * ACT_STR + r0;
                        af[mg][0] = __float_as_uint(a0[0]);
                        af[mg][1] = __float_as_uint(a0[8]);
                        af[mg][2] = __float_as_uint(a1[0]);
                        af[mg][3] = __float_as_uint(a1[8]);
                    }
#pragma unroll
                    for (int mg = 0; mg < 2; mg++)
#pragma unroll
                        for (int n8 = 0; n8 < 8; n8++)
                            mma_tf32(acc[mg][n8], af[mg], bf[n8]);
                }
            }
            if (idx < 17) {
                float* d = Bsm + (cur ^ 1) * (ICC * BSTR) + brow * BSTR + bcol;
                d[0] = cvt_tf32(pa.x); d[1] = cvt_tf32(pa.y); d[2] = cvt_tf32(pa.z); d[3] = cvt_tf32(pa.w);
                d[4] = cvt_tf32(pb.x); d[5] = cvt_tf32(pb.y); d[6] = cvt_tf32(pb.z); d[7] = cvt_tf32(pb.w);
            }
            __syncthreads();
            cur ^= 1;
        }
    }

    float* outsm = act;
    if (warp < 7) {
#pragma unroll
        for (int mg = 0; mg < 2; mg++) {
            int r0 = wrow + mg * 16 + g;
#pragma unroll
            for (int n8 = 0; n8 < 8; n8++) {
                int oc = n8 * 8 + 2 * t;
                outsm[oc * OUT_STR + r0] = acc[mg][n8][0];
                outsm[(oc + 1) * OUT_STR + r0] = acc[mg][n8][1];
                outsm[oc * OUT_STR + r0 + 8] = acc[mg][n8][2];
                outsm[(oc + 1) * OUT_STR + r0 + 8] = acc[mg][n8][3];
            }
        }
    }
    __syncthreads();
    for (int i = tid; i < 64 * PP; i += 256) {
        int oc = i / PP, p = i % PP;
        float v = outsm[oc * OUT_STR + (p / OSZ) * 16 + (p % OSZ)];
        g_abuf[((size_t)k * 64 + oc) * PP + p] = v + __ldg(&bias_sem[oc]) + __ldg(&bias_fpn[oc]);
    }
}

// ---------------- aff via tf32 mma + sigmoid + deg partials ----------------
__global__ __launch_bounds__(224)
void k_aff_mma(const float* __restrict__ aff_b) {
    extern __shared__ float dyn[];
    float* sA = dyn;
    float* sW = dyn + 64 * AFF_ASTR;
    int n0 = blockIdx.x * 56;
    int k = blockIdx.y;
    int tid = threadIdx.x;
    int warp = tid >> 5;
    int lane = tid & 31;
    int g = lane >> 2;
    int t = lane & 3;
    int wrow = warp * 32;

    for (int idx = tid; idx < 64 * 224; idx += 224) {
        int c = idx / 224, p = idx % 224;
        float v = 0.f;
        if (p < PP) {
            float a = g_abuf[((size_t)k * 64 + c) * PP + p];
            v = fmaxf(a * g_sc_aff[c] + g_sh_aff[c], 0.f);
        }
        sA[c * AFF_ASTR + p] = cvt_tf32(v);
    }
    for (int idx = tid; idx < 64 * 56; idx += 224) {
        int c = idx / 56, nn = idx % 56;
        int n = n0 + nn;
        float v = (n < PP) ? g_waffT[c * PP + n] : 0.f;
        sW[c * AFF_WSTR + nn] = cvt_tf32(v);
    }
    __syncthreads();

    float acc[2][7][4];
#pragma unroll
    for (int mg = 0; mg < 2; mg++)
#pragma unroll
        for (int n8 = 0; n8 < 7; n8++)
#pragma unroll
            for (int q = 0; q < 4; q++) acc[mg][n8][q] = 0.f;

#pragma unroll
    for (int ks = 0; ks < 8; ks++) {
        unsigned bf[7][2];
#pragma unroll
        for (int n8 = 0; n8 < 7; n8++) {
            bf[n8][0] = __float_as_uint(sW[(ks * 8 + t) * AFF_WSTR + n8 * 8 + g]);
            bf[n8][1] = __float_as_uint(sW[(ks * 8 + t + 4) * AFF_WSTR + n8 * 8 + g]);
        }
        unsigned af[2][4];
#pragma unroll
        for (int mg = 0; mg < 2; mg++) {
            int r0 = wrow + mg * 16 + g;
            const float* a0 = sA + (ks * 8 + t) * AFF_ASTR + r0;
            const float* a1 = sA + (ks * 8 + t + 4) * AFF_ASTR + r0;
            af[mg][0] = __float_as_uint(a0[0]);
            af[mg][1] = __float_as_uint(a0[8]);
            af[mg][2] = __float_as_uint(a1[0]);
            af[mg][3] = __float_as_uint(a1[8]);
        }
#pragma unroll
        for (int mg = 0; mg < 2; mg++)
#pragma unroll
            for (int n8 = 0; n8 < 7; n8++)
                mma_tf32(acc[mg][n8], af[mg], bf[n8]);
    }

    float* Ak = g_Abuf + (size_t)k * PP * PP;
#pragma unroll
    for (int mg = 0; mg < 2; mg++) {
#pragma unroll
        for (int half = 0; half < 2; half++) {
            int p = wrow + mg * 16 + g + half * 8;
            if (p < PP) {
                float dpart = 0.f;
#pragma unroll
                for (int n8 = 0; n8 < 7; n8++) {
#pragma unroll
                    for (int q = 0; q < 2; q++) {
                        int n = n0 + n8 * 8 + 2 * t + q;
                        if (n < PP) {
                            float v = acc[mg][n8][half * 2 + q] + __ldg(&aff_b[n]);
                            float s = 1.f / (1.f + expf(-v));
                            Ak[(size_t)n * PP + p] = s;
                            dpart += s;
                        }
                    }
                }
                atomicAdd(&g_deg[k * PP + p], dpart);
            }
        }
    }
}

// ---------------- xw1s ----------------
__global__ __launch_bounds__(224)
void k_xw1(const float* __restrict__ rf, const float* __restrict__ w1) {
    __shared__ __align__(16) float sW1[CC * 16];
    int k = blockIdx.x;
    int tid = threadIdx.x;
    for (int i = tid; i < CC * 16; i += 224) sW1[i] = w1[i];
    __syncthreads();
    int i = tid;
    if (i >= PP) return;
    float acc[16];
#pragma unroll
    for (int f = 0; f < 16; f++) acc[f] = 0.f;
    const float* x = rf + (size_t)k * CC * PP;
    for (int c = 0; c < CC; c++) {
        float v = x[c * PP + i];
#pragma unroll
        for (int fg = 0; fg < 4; fg++) {
            float4 w4 = *(const float4*)&sW1[c * 16 + fg * 4];
            acc[fg * 4 + 0] += v * w4.x;
            acc[fg * 4 + 1] += v * w4.y;
            acc[fg * 4 + 2] += v * w4.z;
            acc[fg * 4 + 3] += v * w4.w;
        }
    }
    float di = rsqrtf(g_deg[k * PP + i]);
    float* o = g_xw1 + ((size_t)k * PP + i) * 16;
#pragma unroll
    for (int fg = 0; fg < 4; fg++) {
        float4 v;
        v.x = di * acc[fg * 4 + 0];
        v.y = di * acc[fg * 4 + 1];
        v.z = di * acc[fg * 4 + 2];
        v.w = di * acc[fg * 4 + 3];
        *(float4*)&o[fg * 4] = v;
    }
}

// ---------------- agg1 + relu + (x1 @ w2) scaled ----------------
__global__ __launch_bounds__(224)
void k_gcn1(const float* __restrict__ b1, const float* __restrict__ w2) {
    __shared__ __align__(16) float sXW[PP * 16];
    __shared__ __align__(16) float sW2[16 * CC];
    int k = blockIdx.x;
    int tid = threadIdx.x;
    for (int i = tid; i < PP * 16; i += 224) sXW[i] = g_xw1[(size_t)k * PP * 16 + i];
    for (int i = tid; i < 16 * CC; i += 224) sW2[i] = w2[i];
    __syncthreads();
    int j = tid;
    if (j >= PP) return;
    float acc[16];
#pragma unroll
    for (int f = 0; f < 16; f++) acc[f] = 0.f;
    const float* A = g_Abuf + (size_t)k * PP * PP;
    for (int i = 0; i < PP; i++) {
        float a = A[i * PP + j];
#pragma unroll
        for (int fg = 0; fg < 4; fg++) {
            float4 xv = *(const float4*)&sXW[i * 16 + fg * 4];
            acc[fg * 4 + 0] += a * xv.x;
            acc[fg * 4 + 1] += a * xv.y;
            acc[fg * 4 + 2] += a * xv.z;
            acc[fg * 4 + 3] += a * xv.w;
        }
    }
    float dj = rsqrtf(g_deg[k * PP + j]);
    float x1[16];
#pragma unroll
    for (int f = 0; f < 16; f++) x1[f] = fmaxf(acc[f] * dj + b1[f], 0.f);
    float* o = g_xw2 + ((size_t)k * PP + j) * CC;
    for (int g = 0; g < 64; g++) {
        float4 s = make_float4(0.f, 0.f, 0.f, 0.f);
#pragma unroll
        for (int f = 0; f < 16; f++) {
            float4 w4 = *(const float4*)&sW2[f * CC + g * 4];
            s.x += x1[f] * w4.x;
            s.y += x1[f] * w4.y;
            s.z += x1[f] * w4.z;
            s.w += x1[f] * w4.w;
        }
        s.x *= dj; s.y *= dj; s.z *= dj; s.w *= dj;
        *(float4*)&o[g * 4] = s;
    }
}

// ---------------- agg2 via tf32 mma + bias + add roi_sem -> out ----------------
__global__ __launch_bounds__(224)
void k_gcn2_mma(const float* __restrict__ b2, float* __restrict__ out) {
    __shared__ float sA[32 * G2_ASTR];
    __shared__ float sX[32 * G2_XSTR];
    int f0 = blockIdx.x * 64;
    int k = blockIdx.y;
    int tid = threadIdx.x;
    int warp = tid >> 5;
    int lane = tid & 31;
    int g = lane >> 2;
    int t = lane & 3;
    int wrow = warp * 32;

    float acc[2][8][4];
#pragma unroll
    for (int mg = 0; mg < 2; mg++)
#pragma unroll
        for (int n8 = 0; n8 < 8; n8++)
#pragma unroll
            for (int q = 0; q < 4; q++) acc[mg][n8][q] = 0.f;

    const float* A = g_Abuf + (size_t)k * PP * PP;
    const float* X2 = g_xw2 + (size_t)k * PP * CC;

    for (int i0 = 0; i0 < 224; i0 += 32) {
        __syncthreads();
        for (int ii = 0; ii < 32; ii++) {
            int i = i0 + ii;
            float v = (i < PP && tid < PP) ? A[(size_t)i * PP + tid] : 0.f;
            sA[ii * G2_ASTR + tid] = cvt_tf32(v);
        }
        for (int idx = tid; idx < 32 * 64; idx += 224) {
            int ii = idx >> 6, ff = idx & 63;
            int i = i0 + ii;
            float v = (i < PP) ? X2[(size_t)i * CC + f0 + ff] : 0.f;
            sX[ii * G2_XSTR + ff] = cvt_tf32(v);
        }
        __syncthreads();
#pragma unroll
        for (int ks = 0; ks < 4; ks++) {
            unsigned bf[8][2];
#pragma unroll
            for (int n8 = 0; n8 < 8; n8++) {
                bf[n8][0] = __float_as_uint(sX[(ks * 8 + t) * G2_XSTR + n8 * 8 + g]);
                bf[n8][1] = __float_as_uint(sX[(ks * 8 + t + 4) * G2_XSTR + n8 * 8 + g]);
            }
            unsigned af[2][4];
#pragma unroll
            for (int mg = 0; mg < 2; mg++) {
                int r0 = wrow + mg * 16 + g;
                const float* a0 = sA + (ks * 8 + t) * G2_ASTR + r0;
                const float* a1 = sA + (ks * 8 + t + 4) * G2_ASTR + r0;
                af[mg][0] = __float_as_uint(a0[0]);
                af[mg][1] = __float_as_uint(a0[8]);
                af[mg][2] = __float_as_uint(a1[0]);
                af[mg][3] = __float_as_uint(a1[8]);
            }
#pragma unroll
            for (int mg = 0; mg < 2; mg++)
#pragma unroll
                for (int n8 = 0; n8 < 8; n8++)
                    mma_tf32(acc[mg][n8], af[mg], bf[n8]);
        }
    }

#pragma unroll
    for (int mg = 0; mg < 2; mg++) {
#pragma unroll
        for (int half = 0; half < 2; half++) {
            int j = wrow + mg * 16 + g + half * 8;
            if (j < PP) {
                float dj = rsqrtf(g_deg[k * PP + j]);
                const float* rs = g_roisem + ((size_t)k * PP + j) * CC;
#pragma unroll
                for (int n8 = 0; n8 < 8; n8++) {
                    int f = f0 + n8 * 8 + 2 * t;
                    float v0 = acc[mg][n8][half * 2 + 0];
                    float v1 = acc[mg][n8][half * 2 + 1];
                    out[((size_t)k * CC + f) * PP + j] = rs[f] + dj * v0 + __ldg(&b2[f]);
                    out[((size_t)k * CC + f + 1) * PP + j] = rs[f + 1] + dj * v1 + __ldg(&b2[f + 1]);
                }
            }
        }
    }
}

// ---------------- launch ----------------
extern "C" void kernel_launch(void* const* d_in, const int* in_sizes, int n_in,
                              void* d_out, int out_size) {
    const float* roi_feature = (const float*)d_in[0];
    const float* semantic = (const float*)d_in[1];
    const float* boxes = (const float*)d_in[2];
    const float* bn_sem_g = (const float*)d_in[3];
    const float* bn_sem_b = (const float*)d_in[4];
    const float* bn_sem_m = (const float*)d_in[5];
    const float* bn_sem_v = (const float*)d_in[6];
    const float* conv_sem_w = (const float*)d_in[7];
    const float* conv_sem_b = (const float*)d_in[8];
    const float* bn_fpn_g = (const float*)d_in[9];
    const float* bn_fpn_b = (const float*)d_in[10];
    const float* bn_fpn_m = (const float*)d_in[11];
    const float* bn_fpn_v = (const float*)d_in[12];
    const float* conv_fpn_w = (const float*)d_in[13];
    const float* conv_fpn_b = (const float*)d_in[14];
    const float* bn_aff_g = (const float*)d_in[15];
    const float* bn_aff_b = (const float*)d_in[16];
    const float* bn_aff_m = (const float*)d_in[17];
    const float* bn_aff_v = (const float*)d_in[18];
    const float* conv_aff_w = (const float*)d_in[19];
    const float* conv_aff_b = (const float*)d_in[20];
    const float* gcn1_w = (const float*)d_in[21];
    const float* gcn1_b = (const float*)d_in[22];
    const float* gcn2_w = (const float*)d_in[23];
    const float* gcn2_b = (const float*)d_in[24];
    float* out = (float*)d_out;

    static int smem_set = 0;
    if (!smem_set) {
        cudaFuncSetAttribute(k_conv_mma, cudaFuncAttributeMaxDynamicSharedMemorySize, CONV_SMEM);
        cudaFuncSetAttribute(k_aff_mma, cudaFuncAttributeMaxDynamicSharedMemorySize, AFF_SMEM);
        smem_set = 1;
    }

    k_prep_all<<<KK + 1 + 128, 256>>>(boxes,
                                      bn_sem_g, bn_sem_b, bn_sem_m, bn_sem_v,
                                      bn_fpn_g, bn_fpn_b, bn_fpn_m, bn_fpn_v,
                                      bn_aff_g, bn_aff_b, bn_aff_m, bn_aff_v,
                                      conv_sem_w, conv_fpn_w, conv_aff_w);
    {
        dim3 g(HWSZ / 32, CC / 32, BB);
        dim3 b(32, 8);
        k_trans_sem<<<g, b>>>(semantic);
    }
    {
        dim3 g(7, KK);
        k_roialign<<<g, 256>>>();
    }
    k_conv_mma<<<KK, 256, CONV_SMEM>>>(roi_feature, conv_sem_b, conv_fpn_b);
    {
        dim3 g(4, KK);
        k_aff_mma<<<g, 224, AFF_SMEM>>>(conv_aff_b);
    }
    k_xw1<<<KK, 224>>>(roi_feature, gcn1_w);
    k_gcn1<<<KK, 224>>>(gcn1_b, gcn2_w);
    {
        dim3 g(4, KK);
        k_gcn2_mma<<<g, 224>>>(gcn2_b, out);
    }
}

// round 8
// speedup vs baseline: 3.2827x; 1.1983x over previous
#include <cuda_runtime.h>
#include <cuda_bf16.h>
#include <math.h>

#define KK 256
#define CC 256
#define PP 196
#define OSZ 14
#define HH 112
#define WW 112
#define BB 4
#define HWSZ 12544

// conv-mma geometry (bf16)
#define ACT_STRW 296              // word stride, mod 32 == 8 -> conflict-free frag loads
#define GUARD 17
#define BWSTR 72                  // B word stride, mod 32 == 8
#define ACT_WORDS (32 * ACT_STRW) // 2 branches x 16 ch-pairs
#define B_WORDS (2 * 16 * BWSTR)  // double-buffered
#define CONV_SMEM ((ACT_WORDS + B_WORDS) * 4)
#define OUT2_STR 233

// gcn2-mma geometry
#define G2_ASTR 232
#define G2_XSTR 72

// aff-mma geometry
#define AFF_ASTR 232
#define AFF_WSTR 72
#define AFF_SMEM ((64 * AFF_ASTR + 64 * AFF_WSTR) * 4)

// ---------------- scratch ----------------
__device__ float g_semT[BB * HWSZ * CC];
__device__ float g_roisem[KK * PP * CC];
__device__ float g_abuf[KK * 64 * PP];
__device__ float g_Abuf[KK * PP * PP];
__device__ float g_deg[KK * PP];
__device__ float g_xw1[KK * PP * 16];
__device__ float g_xw2[KK * PP * CC];
__device__ unsigned g_wsemP[128 * 9 * 64];   // bf16x2 [icpair][tap][oc]
__device__ unsigned g_wfpnP[128 * 9 * 64];
__device__ float g_waffT[64 * PP];
__device__ int   g_tapoff[KK * PP * 16];
__device__ float g_tapw[KK * PP * 16];
__device__ float g_sc_sem[CC], g_sh_sem[CC];
__device__ float g_sc_fpn[CC], g_sh_fpn[CC];
__device__ float g_sc_aff[64], g_sh_aff[64];

__device__ __forceinline__ float cvt_tf32(float x) {
    unsigned r;
    asm("cvt.rna.tf32.f32 %0, %1;" : "=r"(r) : "f"(x));
    return __uint_as_float(r);
}

__device__ __forceinline__ unsigned pack_bf2(float a, float b) {
    __nv_bfloat162 h = __floats2bfloat162_rn(a, b);
    return *(unsigned*)&h;
}

__device__ __forceinline__ void mma_tf32(float* c, const unsigned* a, const unsigned* b) {
    asm volatile(
        "mma.sync.aligned.m16n8k8.row.col.f32.tf32.tf32.f32 "
        "{%0,%1,%2,%3}, {%4,%5,%6,%7}, {%8,%9}, {%0,%1,%2,%3};"
        : "+f"(c[0]), "+f"(c[1]), "+f"(c[2]), "+f"(c[3])
        : "r"(a[0]), "r"(a[1]), "r"(a[2]), "r"(a[3]), "r"(b[0]), "r"(b[1]));
}

__device__ __forceinline__ void mma_bf16(float* c, const unsigned* a, const unsigned* b) {
    asm volatile(
        "mma.sync.aligned.m16n8k16.row.col.f32.bf16.bf16.f32 "
        "{%0,%1,%2,%3}, {%4,%5,%6,%7}, {%8,%9}, {%0,%1,%2,%3};"
        : "+f"(c[0]), "+f"(c[1]), "+f"(c[2]), "+f"(c[3])
        : "r"(a[0]), "r"(a[1]), "r"(a[2]), "r"(a[3]), "r"(b[0]), "r"(b[1]));
}

// ---------------- merged prep ----------------
__global__ void k_prep_all(const float* __restrict__ boxes,
                           const float* gs, const float* bs, const float* ms, const float* vs,
                           const float* gf, const float* bfn, const float* mf, const float* vf,
                           const float* ga, const float* ba, const float* ma, const float* va,
                           const float* wsem, const float* wfpn, const float* waff) {
    int bid = blockIdx.x;
    int tid = threadIdx.x;
    if (bid < KK) {
        int k = bid;
        int p = tid;
        if (p >= PP) return;
        g_deg[k * PP + p] = 0.f;
        int bidx = (int)boxes[k * 5 + 0];
        float x1 = boxes[k * 5 + 1], y1 = boxes[k * 5 + 2];
        float x2 = boxes[k * 5 + 3], y2 = boxes[k * 5 + 4];
        float bw = fmaxf(x2 - x1, 1.f) * (1.f / OSZ);
        float bh = fmaxf(y2 - y1, 1.f) * (1.f / OSZ);
        int oy = p / OSZ, ox = p % OSZ;
        int base = bidx * HWSZ * CC;
        int* toff = g_tapoff + ((size_t)k * PP + p) * 16;
        float* tw = g_tapw + ((size_t)k * PP + p) * 16;
#pragma unroll
        for (int s = 0; s < 4; s++) {
            int sy = oy * 2 + (s >> 1);
            int sx = ox * 2 + (s & 1);
            float yv = y1 + bh * ((sy + 0.5f) * 0.5f);
            float xv = x1 + bw * ((sx + 0.5f) * 0.5f);
            bool m = (yv >= -1.f) && (yv <= (float)HH) && (xv >= -1.f) && (xv <= (float)WW);
            float yc = fminf(fmaxf(yv, 0.f), (float)(HH - 1));
            float xc = fminf(fmaxf(xv, 0.f), (float)(WW - 1));
            int yl = (int)floorf(yc);
            int xl = (int)floorf(xc);
            int yh = min(yl + 1, HH - 1);
            int xh = min(xl + 1, WW - 1);
            float ly = yc - (float)yl;
            float lx = xc - (float)xl;
            float sc = m ? 0.25f : 0.f;
            toff[s * 4 + 0] = base + (yl * WW + xl) * CC;
            toff[s * 4 + 1] = base + (yl * WW + xh) * CC;
            toff[s * 4 + 2] = base + (yh * WW + xl) * CC;
            toff[s * 4 + 3] = base + (yh * WW + xh) * CC;
            tw[s * 4 + 0] = sc * (1.f - ly) * (1.f - lx);
            tw[s * 4 + 1] = sc * (1.f - ly) * lx;
            tw[s * 4 + 2] = sc * ly * (1.f - lx);
            tw[s * 4 + 3] = sc * ly * lx;
        }
    } else if (bid == KK) {
        int t = tid;
        if (t < CC) {
            float s = gs[t] * rsqrtf(vs[t] + 1e-5f);
            g_sc_sem[t] = s;
            g_sh_sem[t] = bs[t] - ms[t] * s;
            float f = gf[t] * rsqrtf(vf[t] + 1e-5f);
            g_sc_fpn[t] = f;
            g_sh_fpn[t] = bfn[t] - mf[t] * f;
        }
        if (t < 64) {
            float a = ga[t] * rsqrtf(va[t] + 1e-5f);
            g_sc_aff[t] = a;
            g_sh_aff[t] = ba[t] - ma[t] * a;
        }
    } else {
        const int NW = 128 * 9 * 64;  // 73728 packed words per branch
        const int NA = 64 * PP;
        int total = 2 * NW + NA;
        int stride = 128 * 256;
        for (int d = (bid - KK - 1) * 256 + tid; d < total; d += stride) {
            if (d < NW) {
                int cp = d / 576, r = d % 576, tap = r / 64, oc = r % 64;
                g_wsemP[d] = pack_bf2(wsem[oc * (CC * 9) + (2 * cp) * 9 + tap],
                                      wsem[oc * (CC * 9) + (2 * cp + 1) * 9 + tap]);
            } else if (d < 2 * NW) {
                int e = d - NW;
                int cp = e / 576, r = e % 576, tap = r / 64, oc = r % 64;
                g_wfpnP[e] = pack_bf2(wfpn[oc * (CC * 9) + (2 * cp) * 9 + tap],
                                      wfpn[oc * (CC * 9) + (2 * cp + 1) * 9 + tap]);
            } else {
                int e = d - 2 * NW;
                int c = e / PP, n = e % PP;
                g_waffT[e] = waff[n * 64 + c];
            }
        }
    }
}

// ---------------- transpose semantic NCHW -> NHWC ----------------
__global__ void k_trans_sem(const float* __restrict__ sem) {
    __shared__ float tile[32][33];
    int b = blockIdx.z;
    int hw0 = blockIdx.x * 32;
    int c0 = blockIdx.y * 32;
    int tx = threadIdx.x, ty = threadIdx.y;
    const float* src = sem + (size_t)b * CC * HWSZ;
    float* dst = g_semT + (size_t)b * HWSZ * CC;
#pragma unroll
    for (int yy = 0; yy < 32; yy += 8)
        tile[ty + yy][tx] = src[(size_t)(c0 + ty + yy) * HWSZ + hw0 + tx];
    __syncthreads();
#pragma unroll
    for (int yy = 0; yy < 32; yy += 8)
        dst[(size_t)(hw0 + ty + yy) * CC + c0 + tx] = tile[tx][ty + yy];
}

// ---------------- ROI align gather ----------------
__global__ __launch_bounds__(256)
void k_roialign() {
    __shared__ int soff[28 * 16];
    __shared__ float sw[28 * 16];
    int k = blockIdx.y;
    int p0 = blockIdx.x * 28;
    int tid = threadIdx.x;
    for (int i = tid; i < 28 * 16; i += 256) {
        soff[i] = g_tapoff[((size_t)k * PP + p0) * 16 + i];
        sw[i] = g_tapw[((size_t)k * PP + p0) * 16 + i];
    }
    __syncthreads();
    int c = tid;
    for (int pp = 0; pp < 28; pp++) {
        float acc = 0.f;
#pragma unroll
        for (int t = 0; t < 16; t++)
            acc += sw[pp * 16 + t] * __ldg(&g_semT[soff[pp * 16 + t] + c]);
        g_roisem[((size_t)k * PP + p0 + pp) * CC + c] = acc;
    }
}

// ---------------- bf16 tensor-core dual 3x3 conv ----------------
// M = 224 rows (warps 0-6), N = 64 oc, K = 2 br x 9 taps x 256 ic; ic chunked by 32 (16 pairs).
__global__ __launch_bounds__(256, 2)
void k_conv_mma(const float* __restrict__ roi_feature,
                const float* __restrict__ bias_sem, const float* __restrict__ bias_fpn) {
    extern __shared__ float dyn[];
    unsigned* act = (unsigned*)dyn;          // [2 br][16 cp][ACT_STRW]
    unsigned* Bw = act + ACT_WORDS;          // [2 buf][16 cp][BWSTR]
    int k = blockIdx.x;
    int tid = threadIdx.x;
    int warp = tid >> 5;
    int lane = tid & 31;
    int g = lane >> 2;
    int t = lane & 3;
    int wrow = warp * 32;

    float acc[2][8][4];
#pragma unroll
    for (int mg = 0; mg < 2; mg++)
#pragma unroll
        for (int n8 = 0; n8 < 8; n8++)
#pragma unroll
            for (int q = 0; q < 4; q++) acc[mg][n8][q] = 0.f;

    const float* rfk = roi_feature + (size_t)k * CC * PP;
    const float* rsk = g_roisem + (size_t)k * PP * CC;

    // zero act once (guards persist; interior fully rewritten per chunk)
    for (int i = tid; i < ACT_WORDS; i += 256) act[i] = 0u;
    __syncthreads();

    for (int ic0 = 0; ic0 < CC; ic0 += 32) {
        int icp0 = ic0 >> 1;
        // sem branch: thread handles (p, channel-pair): float2 NHWC load, pack bf16x2
        for (int i = tid; i < PP * 16; i += 256) {
            int p = i >> 4, cp = i & 15;
            int c = ic0 + 2 * cp;
            float2 v2 = *(const float2*)&rsk[(size_t)p * CC + c];
            float v0 = fmaxf(v2.x * g_sc_sem[c] + g_sh_sem[c], 0.f);
            float v1 = fmaxf(v2.y * g_sc_sem[c + 1] + g_sh_sem[c + 1], 0.f);
            act[cp * ACT_STRW + GUARD + (p / OSZ) * 16 + (p % OSZ)] = pack_bf2(v0, v1);
        }
        // fpn branch: NCHW, two coalesced loads per pair
        for (int i = tid; i < 16 * PP; i += 256) {
            int cp = i / PP, p = i % PP;
            int c = ic0 + 2 * cp;
            float v0 = fmaxf(rfk[(size_t)c * PP + p] * g_sc_fpn[c] + g_sh_fpn[c], 0.f);
            float v1 = fmaxf(rfk[(size_t)(c + 1) * PP + p] * g_sc_fpn[c + 1] + g_sh_fpn[c + 1], 0.f);
            act[(16 + cp) * ACT_STRW + GUARD + (p / OSZ) * 16 + (p % OSZ)] = pack_bf2(v0, v1);
        }
        // stage first B tile (br0, tap0) into buf 0: 1024 words, 4/thread
#pragma unroll
        for (int j = 0; j < 4; j++) {
            int id2 = tid + j * 256;
            int cp = id2 >> 6, oc = id2 & 63;
            Bw[cp * BWSTR + oc] = g_wsemP[(size_t)(icp0 + cp) * 576 + 0 * 64 + oc];
        }
        __syncthreads();

        int cur = 0;
        for (int idx = 0; idx < 18; idx++) {
            int br = idx / 9, tap = idx % 9;
            int off = (tap / 3 - 1) * 16 + (tap % 3 - 1);
            unsigned pw[4];
            if (idx < 17) {
                int nbr = (idx + 1) / 9, ntap = (idx + 1) % 9;
                const unsigned* wP = nbr ? g_wfpnP : g_wsemP;
#pragma unroll
                for (int j = 0; j < 4; j++) {
                    int id2 = tid + j * 256;
                    int cp = id2 >> 6, oc = id2 & 63;
                    pw[j] = wP[(size_t)(icp0 + cp) * 576 + ntap * 64 + oc];
                }
            }
            if (warp < 7) {
                const unsigned* actb = act + br * (16 * ACT_STRW);
                const unsigned* Bc = Bw + cur * (16 * BWSTR);
#pragma unroll
                for (int s = 0; s < 2; s++) {
                    unsigned bf[8][2];
#pragma unroll
                    for (int n8 = 0; n8 < 8; n8++) {
                        bf[n8][0] = Bc[(s * 8 + t) * BWSTR + n8 * 8 + g];
                        bf[n8][1] = Bc[(s * 8 + t + 4) * BWSTR + n8 * 8 + g];
                    }
                    unsigned af[2][4];
#pragma unroll
                    for (int mg = 0; mg < 2; mg++) {
                        int r0 = GUARD + wrow + mg * 16 + g + off;
                        const unsigned* a0 = actb + (s * 8 + t) * ACT_STRW + r0;
                        const unsigned* a1 = actb + (s * 8 + t + 4) * ACT_STRW + r0;
                        af[mg][0] = a0[0];
                        af[mg][1] = a0[8];
                        af[mg][2] = a1[0];
                        af[mg][3] = a1[8];
                    }
#pragma unroll
                    for (int mg = 0; mg < 2; mg++)
#pragma unroll
                        for (int n8 = 0; n8 < 8; n8++)
                            mma_bf16(acc[mg][n8], af[mg], bf[n8]);
                }
            }
            if (idx < 17) {
                unsigned* d = Bw + (cur ^ 1) * (16 * BWSTR);
#pragma unroll
                for (int j = 0; j < 4; j++) {
                    int id2 = tid + j * 256;
                    d[(id2 >> 6) * BWSTR + (id2 & 63)] = pw[j];
                }
            }
            __syncthreads();
            cur ^= 1;
        }
    }

    // epilogue: two 32-oc passes through smem (smem too small for 64 rows now)
    float* outsm = dyn;
#pragma unroll
    for (int og = 0; og < 2; og++) {
        __syncthreads();
        if (warp < 7) {
#pragma unroll
            for (int mg = 0; mg < 2; mg++) {
                int r0 = wrow + mg * 16 + g;
#pragma unroll
                for (int nn = 0; nn < 4; nn++) {
                    int n8 = og * 4 + nn;
                    int ocl = nn * 8 + 2 * t;
                    outsm[ocl * OUT2_STR + r0] = acc[mg][n8][0];
                    outsm[(ocl + 1) * OUT2_STR + r0] = acc[mg][n8][1];
                    outsm[ocl * OUT2_STR + r0 + 8] = acc[mg][n8][2];
                    outsm[(ocl + 1) * OUT2_STR + r0 + 8] = acc[mg][n8][3];
                }
            }
        }
        __syncthreads();
        for (int i = tid; i < 32 * PP; i += 256) {
            int ocl = i / PP, p = i % PP;
            int oc = og * 32 + ocl;
            float v = outsm[ocl * OUT2_STR + (p / OSZ) * 16 + (p % OSZ)];
            g_abuf[((size_t)k * 64 + oc) * PP + p] = v + __ldg(&bias_sem[oc]) + __ldg(&bias_fpn[oc]);
        }
    }
}

// ---------------- aff via tf32 mma + sigmoid + deg partials ----------------
__global__ __launch_bounds__(224)
void k_aff_mma(const float* __restrict__ aff_b) {
    extern __shared__ float dyn[];
    float* sA = dyn;
    float* sW = dyn + 64 * AFF_ASTR;
    int n0 = blockIdx.x * 56;
    int k = blockIdx.y;
    int tid = threadIdx.x;
    int warp = tid >> 5;
    int lane = tid & 31;
    int g = lane >> 2;
    int t = lane & 3;
    int wrow = warp * 32;

    for (int idx = tid; idx < 64 * 224; idx += 224) {
        int c = idx / 224, p = idx % 224;
        float v = 0.f;
        if (p < PP) {
            float a = g_abuf[((size_t)k * 64 + c) * PP + p];
            v = fmaxf(a * g_sc_aff[c] + g_sh_aff[c], 0.f);
        }
        sA[c * AFF_ASTR + p] = cvt_tf32(v);
    }
    for (int idx = tid; idx < 64 * 56; idx += 224) {
        int c = idx / 56, nn = idx % 56;
        int n = n0 + nn;
        float v = (n < PP) ? g_waffT[c * PP + n] : 0.f;
        sW[c * AFF_WSTR + nn] = cvt_tf32(v);
    }
    __syncthreads();

    float acc[2][7][4];
#pragma unroll
    for (int mg = 0; mg < 2; mg++)
#pragma unroll
        for (int n8 = 0; n8 < 7; n8++)
#pragma unroll
            for (int q = 0; q < 4; q++) acc[mg][n8][q] = 0.f;

#pragma unroll
    for (int ks = 0; ks < 8; ks++) {
        unsigned bf[7][2];
#pragma unroll
        for (int n8 = 0; n8 < 7; n8++) {
            bf[n8][0] = __float_as_uint(sW[(ks * 8 + t) * AFF_WSTR + n8 * 8 + g]);
            bf[n8][1] = __float_as_uint(sW[(ks * 8 + t + 4) * AFF_WSTR + n8 * 8 + g]);
        }
        unsigned af[2][4];
#pragma unroll
        for (int mg = 0; mg < 2; mg++) {
            int r0 = wrow + mg * 16 + g;
            const float* a0 = sA + (ks * 8 + t) * AFF_ASTR + r0;
            const float* a1 = sA + (ks * 8 + t + 4) * AFF_ASTR + r0;
            af[mg][0] = __float_as_uint(a0[0]);
            af[mg][1] = __float_as_uint(a0[8]);
            af[mg][2] = __float_as_uint(a1[0]);
            af[mg][3] = __float_as_uint(a1[8]);
        }
#pragma unroll
        for (int mg = 0; mg < 2; mg++)
#pragma unroll
            for (int n8 = 0; n8 < 7; n8++)
                mma_tf32(acc[mg][n8], af[mg], bf[n8]);
    }

    float* Ak = g_Abuf + (size_t)k * PP * PP;
#pragma unroll
    for (int mg = 0; mg < 2; mg++) {
#pragma unroll
        for (int half = 0; half < 2; half++) {
            int p = wrow + mg * 16 + g + half * 8;
            if (p < PP) {
                float dpart = 0.f;
#pragma unroll
                for (int n8 = 0; n8 < 7; n8++) {
#pragma unroll
                    for (int q = 0; q < 2; q++) {
                        int n = n0 + n8 * 8 + 2 * t + q;
                        if (n < PP) {
                            float v = acc[mg][n8][half * 2 + q] + __ldg(&aff_b[n]);
                            float s = 1.f / (1.f + expf(-v));
                            Ak[(size_t)n * PP + p] = s;
                            dpart += s;
                        }
                    }
                }
                atomicAdd(&g_deg[k * PP + p], dpart);
            }
        }
    }
}

// ---------------- xw1s ----------------
__global__ __launch_bounds__(224)
void k_xw1(const float* __restrict__ rf, const float* __restrict__ w1) {
    __shared__ __align__(16) float sW1[CC * 16];
    int k = blockIdx.x;
    int tid = threadIdx.x;
    for (int i = tid; i < CC * 16; i += 224) sW1[i] = w1[i];
    __syncthreads();
    int i = tid;
    if (i >= PP) return;
    float acc[16];
#pragma unroll
    for (int f = 0; f < 16; f++) acc[f] = 0.f;
    const float* x = rf + (size_t)k * CC * PP;
    for (int c = 0; c < CC; c++) {
        float v = x[c * PP + i];
#pragma unroll
        for (int fg = 0; fg < 4; fg++) {
            float4 w4 = *(const float4*)&sW1[c * 16 + fg * 4];
            acc[fg * 4 + 0] += v * w4.x;
            acc[fg * 4 + 1] += v * w4.y;
            acc[fg * 4 + 2] += v * w4.z;
            acc[fg * 4 + 3] += v * w4.w;
        }
    }
    float di = rsqrtf(g_deg[k * PP + i]);
    float* o = g_xw1 + ((size_t)k * PP + i) * 16;
#pragma unroll
    for (int fg = 0; fg < 4; fg++) {
        float4 v;
        v.x = di * acc[fg * 4 + 0];
        v.y = di * acc[fg * 4 + 1];
        v.z = di * acc[fg * 4 + 2];
        v.w = di * acc[fg * 4 + 3];
        *(float4*)&o[fg * 4] = v;
    }
}

// ---------------- agg1 + relu + (x1 @ w2) scaled ----------------
__global__ __launch_bounds__(224)
void k_gcn1(const float* __restrict__ b1, const float* __restrict__ w2) {
    __shared__ __align__(16) float sXW[PP * 16];
    __shared__ __align__(16) float sW2[16 * CC];
    int k = blockIdx.x;
    int tid = threadIdx.x;
    for (int i = tid; i < PP * 16; i += 224) sXW[i] = g_xw1[(size_t)k * PP * 16 + i];
    for (int i = tid; i < 16 * CC; i += 224) sW2[i] = w2[i];
    __syncthreads();
    int j = tid;
    if (j >= PP) return;
    float acc[16];
#pragma unroll
    for (int f = 0; f < 16; f++) acc[f] = 0.f;
    const float* A = g_Abuf + (size_t)k * PP * PP;
    for (int i = 0; i < PP; i++) {
        float a = A[i * PP + j];
#pragma unroll
        for (int fg = 0; fg < 4; fg++) {
            float4 xv = *(const float4*)&sXW[i * 16 + fg * 4];
            acc[fg * 4 + 0] += a * xv.x;
            acc[fg * 4 + 1] += a * xv.y;
            acc[fg * 4 + 2] += a * xv.z;
            acc[fg * 4 + 3] += a * xv.w;
        }
    }
    float dj = rsqrtf(g_deg[k * PP + j]);
    float x1[16];
#pragma unroll
    for (int f = 0; f < 16; f++) x1[f] = fmaxf(acc[f] * dj + b1[f], 0.f);
    float* o = g_xw2 + ((size_t)k * PP + j) * CC;
    for (int g = 0; g < 64; g++) {
        float4 s = make_float4(0.f, 0.f, 0.f, 0.f);
#pragma unroll
        for (int f = 0; f < 16; f++) {
            float4 w4 = *(const float4*)&sW2[f * CC + g * 4];
            s.x += x1[f] * w4.x;
            s.y += x1[f] * w4.y;
            s.z += x1[f] * w4.z;
            s.w += x1[f] * w4.w;
        }
        s.x *= dj; s.y *= dj; s.z *= dj; s.w *= dj;
        *(float4*)&o[g * 4] = s;
    }
}

// ---------------- agg2 via tf32 mma + bias + add roi_sem -> out ----------------
__global__ __launch_bounds__(224)
void k_gcn2_mma(const float* __restrict__ b2, float* __restrict__ out) {
    __shared__ float sA[32 * G2_ASTR];
    __shared__ float sX[32 * G2_XSTR];
    int f0 = blockIdx.x * 64;
    int k = blockIdx.y;
    int tid = threadIdx.x;
    int warp = tid >> 5;
    int lane = tid & 31;
    int g = lane >> 2;
    int t = lane & 3;
    int wrow = warp * 32;

    float acc[2][8][4];
#pragma unroll
    for (int mg = 0; mg < 2; mg++)
#pragma unroll
        for (int n8 = 0; n8 < 8; n8++)
#pragma unroll
            for (int q = 0; q < 4; q++) acc[mg][n8][q] = 0.f;

    const float* A = g_Abuf + (size_t)k * PP * PP;
    const float* X2 = g_xw2 + (size_t)k * PP * CC;

    for (int i0 = 0; i0 < 224; i0 += 32) {
        __syncthreads();
        for (int ii = 0; ii < 32; ii++) {
            int i = i0 + ii;
            float v = (i < PP && tid < PP) ? A[(size_t)i * PP + tid] : 0.f;
            sA[ii * G2_ASTR + tid] = cvt_tf32(v);
        }
        for (int idx = tid; idx < 32 * 64; idx += 224) {
            int ii = idx >> 6, ff = idx & 63;
            int i = i0 + ii;
            float v = (i < PP) ? X2[(size_t)i * CC + f0 + ff] : 0.f;
            sX[ii * G2_XSTR + ff] = cvt_tf32(v);
        }
        __syncthreads();
#pragma unroll
        for (int ks = 0; ks < 4; ks++) {
            unsigned bf[8][2];
#pragma unroll
            for (int n8 = 0; n8 < 8; n8++) {
                bf[n8][0] = __float_as_uint(sX[(ks * 8 + t) * G2_XSTR + n8 * 8 + g]);
                bf[n8][1] = __float_as_uint(sX[(ks * 8 + t + 4) * G2_XSTR + n8 * 8 + g]);
            }
            unsigned af[2][4];
#pragma unroll
            for (int mg = 0; mg < 2; mg++) {
                int r0 = wrow + mg * 16 + g;
                const float* a0 = sA + (ks * 8 + t) * G2_ASTR + r0;
                const float* a1 = sA + (ks * 8 + t + 4) * G2_ASTR + r0;
                af[mg][0] = __float_as_uint(a0[0]);
                af[mg][1] = __float_as_uint(a0[8]);
                af[mg][2] = __float_as_uint(a1[0]);
                af[mg][3] = __float_as_uint(a1[8]);
            }
#pragma unroll
            for (int mg = 0; mg < 2; mg++)
#pragma unroll
                for (int n8 = 0; n8 < 8; n8++)
                    mma_tf32(acc[mg][n8], af[mg], bf[n8]);
        }
    }

#pragma unroll
    for (int mg = 0; mg < 2; mg++) {
#pragma unroll
        for (int half = 0; half < 2; half++) {
            int j = wrow + mg * 16 + g + half * 8;
            if (j < PP) {
                float dj = rsqrtf(g_deg[k * PP + j]);
                const float* rs = g_roisem + ((size_t)k * PP + j) * CC;
#pragma unroll
                for (int n8 = 0; n8 < 8; n8++) {
                    int f = f0 + n8 * 8 + 2 * t;
                    float v0 = acc[mg][n8][half * 2 + 0];
                    float v1 = acc[mg][n8][half * 2 + 1];
                    out[((size_t)k * CC + f) * PP + j] = rs[f] + dj * v0 + __ldg(&b2[f]);
                    out[((size_t)k * CC + f + 1) * PP + j] = rs[f + 1] + dj * v1 + __ldg(&b2[f + 1]);
                }
            }
        }
    }
}

// ---------------- launch ----------------
extern "C" void kernel_launch(void* const* d_in, const int* in_sizes, int n_in,
                              void* d_out, int out_size) {
    const float* roi_feature = (const float*)d_in[0];
    const float* semantic = (const float*)d_in[1];
    const float* boxes = (const float*)d_in[2];
    const float* bn_sem_g = (const float*)d_in[3];
    const float* bn_sem_b = (const float*)d_in[4];
    const float* bn_sem_m = (const float*)d_in[5];
    const float* bn_sem_v = (const float*)d_in[6];
    const float* conv_sem_w = (const float*)d_in[7];
    const float* conv_sem_b = (const float*)d_in[8];
    const float* bn_fpn_g = (const float*)d_in[9];
    const float* bn_fpn_b = (const float*)d_in[10];
    const float* bn_fpn_m = (const float*)d_in[11];
    const float* bn_fpn_v = (const float*)d_in[12];
    const float* conv_fpn_w = (const float*)d_in[13];
    const float* conv_fpn_b = (const float*)d_in[14];
    const float* bn_aff_g = (const float*)d_in[15];
    const float* bn_aff_b = (const float*)d_in[16];
    const float* bn_aff_m = (const float*)d_in[17];
    const float* bn_aff_v = (const float*)d_in[18];
    const float* conv_aff_w = (const float*)d_in[19];
    const float* conv_aff_b = (const float*)d_in[20];
    const float* gcn1_w = (const float*)d_in[21];
    const float* gcn1_b = (const float*)d_in[22];
    const float* gcn2_w = (const float*)d_in[23];
    const float* gcn2_b = (const float*)d_in[24];
    float* out = (float*)d_out;

    static int smem_set = 0;
    if (!smem_set) {
        cudaFuncSetAttribute(k_conv_mma, cudaFuncAttributeMaxDynamicSharedMemorySize, CONV_SMEM);
        cudaFuncSetAttribute(k_aff_mma, cudaFuncAttributeMaxDynamicSharedMemorySize, AFF_SMEM);
        smem_set = 1;
    }

    k_prep_all<<<KK + 1 + 128, 256>>>(boxes,
                                      bn_sem_g, bn_sem_b, bn_sem_m, bn_sem_v,
                                      bn_fpn_g, bn_fpn_b, bn_fpn_m, bn_fpn_v,
                                      bn_aff_g, bn_aff_b, bn_aff_m, bn_aff_v,
                                      conv_sem_w, conv_fpn_w, conv_aff_w);
    {
        dim3 g(HWSZ / 32, CC / 32, BB);
        dim3 b(32, 8);
        k_trans_sem<<<g, b>>>(semantic);
    }
    {
        dim3 g(7, KK);
        k_roialign<<<g, 256>>>();
    }
    k_conv_mma<<<KK, 256, CONV_SMEM>>>(roi_feature, conv_sem_b, conv_fpn_b);
    {
        dim3 g(4, KK);
        k_aff_mma<<<g, 224, AFF_SMEM>>>(conv_aff_b);
    }
    k_xw1<<<KK, 224>>>(roi_feature, gcn1_w);
    k_gcn1<<<KK, 224>>>(gcn1_b, gcn2_w);
    {
        dim3 g(4, KK);
        k_gcn2_mma<<<g, 224>>>(gcn2_b, out);
    }
}